// round 6
// baseline (speedup 1.0000x reference)
#include <cuda_runtime.h>
#include <cstdint>
#include <cstddef>

#define N_TOK 32768
#define HDIM  2048
#define H2DIM 1024
#define NEXP  8

// Scratch (no cudaMalloc allowed)
__device__ float g_h[(size_t)N_TOK * H2DIM];   // post-GELU hidden, 134 MB
__device__ float g_si[N_TOK];                  // rsqrt(var+eps)
__device__ float g_ti[N_TOK];                  // mu * rsqrt(var+eps)
__device__ float g_sums[NEXP];                 // per-expert weight sums

// ---------------- packed fp32x2 helpers (sm_100+) ----------------
#define PACK2(out, a) \
    asm("mov.b64 %0, {%1, %1};" : "=l"(out) : "r"(__float_as_uint(a)))
#define FMA2(d, a, b) \
    asm("fma.rn.f32x2 %0, %1, %2, %0;" : "+l"(d) : "l"(a), "l"(b))

// ---------------- Kernel 1: LayerNorm statistics ----------------
__global__ __launch_bounds__(256)
void ln_stats_kernel(const float* __restrict__ x)
{
    int warp = threadIdx.x >> 5, lane = threadIdx.x & 31;
    int token = blockIdx.x * 8 + warp;
    const float* row = x + (size_t)token * HDIM;
    float s = 0.f, sq = 0.f;
#pragma unroll
    for (int j = 0; j < 16; j++) {
        float4 v = *(const float4*)&row[lane * 4 + j * 128];
        s += v.x + v.y + v.z + v.w;
        sq = fmaf(v.x, v.x, fmaf(v.y, v.y, fmaf(v.z, v.z, fmaf(v.w, v.w, sq))));
    }
#pragma unroll
    for (int off = 16; off; off >>= 1) {
        s  += __shfl_xor_sync(0xFFFFFFFFu, s, off);
        sq += __shfl_xor_sync(0xFFFFFFFFu, sq, off);
    }
    if (lane == 0) {
        float mu  = s * (1.0f / 2048.0f);
        float var = sq * (1.0f / 2048.0f) - mu * mu;
        float v = var + 1e-5f;
        float r = rsqrtf(v);
        r = r * (1.5f - 0.5f * v * r * r);   // Newton refine -> ~IEEE accuracy
        g_si[token] = r;
        g_ti[token] = mu * r;
    }
}

// ---------------- Kernel 2: fused LN-apply + GEMM1 + bias + exact GELU ----------------
// C[m,n] = gelu( sum_k ((si[m]*x[m,k]-ti[m])*lnw[k]+lnb[k]) * w1[n,k] + b1[n] )
// Block tile 128x128, K-tile 16, 256 threads, 8x8 per-thread via fp32x2 pairs.
__global__ __launch_bounds__(256, 2)
void gemm1_kernel(const float* __restrict__ x,
                  const float* __restrict__ lnw,
                  const float* __restrict__ lnb,
                  const float* __restrict__ w1,
                  const float* __restrict__ bias1)
{
    __shared__ __align__(16) float As[2][16][132];
    __shared__ __align__(16) float Bs[2][16][132];

    const int tid = threadIdx.x;
    const int m0 = blockIdx.y * 128;
    const int n0 = blockIdx.x * 128;

    // loader mapping: thread owns float4 (r0, c4..c4+3) in rows r0 and r0+64
    const int r0 = tid >> 2;           // 0..63
    const int c4 = (tid & 3) << 2;     // 0,4,8,12

    const float si0 = g_si[m0 + r0];
    const float ti0 = g_ti[m0 + r0];
    const float si1 = g_si[m0 + r0 + 64];
    const float ti1 = g_ti[m0 + r0 + 64];

    const float* pA0 = x  + (size_t)(m0 + r0)      * HDIM + c4;
    const float* pA1 = x  + (size_t)(m0 + r0 + 64) * HDIM + c4;
    const float* pB0 = w1 + (size_t)(n0 + r0)      * HDIM + c4;
    const float* pB1 = w1 + (size_t)(n0 + r0 + 64) * HDIM + c4;

    const int tx = tid & 15;   // n quadrant
    const int ty = tid >> 4;   // m quadrant

    unsigned long long acc[8][4];
#pragma unroll
    for (int i = 0; i < 8; i++)
#pragma unroll
        for (int j = 0; j < 4; j++) acc[i][j] = 0ULL;

    float4 fa0, fa1, fb0, fb1, flw, flb;

#define STORE_TILE(bb) do { \
    As[bb][c4+0][r0]    = fmaf(flw.x, fmaf(si0, fa0.x, -ti0), flb.x); \
    As[bb][c4+1][r0]    = fmaf(flw.y, fmaf(si0, fa0.y, -ti0), flb.y); \
    As[bb][c4+2][r0]    = fmaf(flw.z, fmaf(si0, fa0.z, -ti0), flb.z); \
    As[bb][c4+3][r0]    = fmaf(flw.w, fmaf(si0, fa0.w, -ti0), flb.w); \
    As[bb][c4+0][r0+64] = fmaf(flw.x, fmaf(si1, fa1.x, -ti1), flb.x); \
    As[bb][c4+1][r0+64] = fmaf(flw.y, fmaf(si1, fa1.y, -ti1), flb.y); \
    As[bb][c4+2][r0+64] = fmaf(flw.z, fmaf(si1, fa1.z, -ti1), flb.z); \
    As[bb][c4+3][r0+64] = fmaf(flw.w, fmaf(si1, fa1.w, -ti1), flb.w); \
    Bs[bb][c4+0][r0]    = fb0.x; \
    Bs[bb][c4+1][r0]    = fb0.y; \
    Bs[bb][c4+2][r0]    = fb0.z; \
    Bs[bb][c4+3][r0]    = fb0.w; \
    Bs[bb][c4+0][r0+64] = fb1.x; \
    Bs[bb][c4+1][r0+64] = fb1.y; \
    Bs[bb][c4+2][r0+64] = fb1.z; \
    Bs[bb][c4+3][r0+64] = fb1.w; \
} while (0)

    // prologue: tile 0
    flw = *(const float4*)(lnw + c4);
    flb = *(const float4*)(lnb + c4);
    fa0 = *(const float4*)(pA0);
    fa1 = *(const float4*)(pA1);
    fb0 = *(const float4*)(pB0);
    fb1 = *(const float4*)(pB1);
    STORE_TILE(0);
    __syncthreads();

    int buf = 0;
#pragma unroll 1
    for (int kt = 0; kt < 128; kt++) {
        if (kt < 127) {
            const int k2 = (kt + 1) * 16;
            flw = *(const float4*)(lnw + k2 + c4);
            flb = *(const float4*)(lnb + k2 + c4);
            fa0 = *(const float4*)(pA0 + k2);
            fa1 = *(const float4*)(pA1 + k2);
            fb0 = *(const float4*)(pB0 + k2);
            fb1 = *(const float4*)(pB1 + k2);
        }
#pragma unroll
        for (int k = 0; k < 16; k++) {
            float4  a0  = *(const float4*)&As[buf][k][ty * 4];
            float4  a1  = *(const float4*)&As[buf][k][ty * 4 + 64];
            double2 bp0 = *(const double2*)&Bs[buf][k][tx * 4];
            double2 bp1 = *(const double2*)&Bs[buf][k][tx * 4 + 64];
            unsigned long long B0 = __double_as_longlong(bp0.x);
            unsigned long long B1 = __double_as_longlong(bp0.y);
            unsigned long long B2 = __double_as_longlong(bp1.x);
            unsigned long long B3 = __double_as_longlong(bp1.y);
#define DOROW(mi, aval) do { \
            unsigned long long Ad_; \
            PACK2(Ad_, aval); \
            FMA2(acc[mi][0], Ad_, B0); \
            FMA2(acc[mi][1], Ad_, B1); \
            FMA2(acc[mi][2], Ad_, B2); \
            FMA2(acc[mi][3], Ad_, B3); \
} while (0)
            DOROW(0, a0.x); DOROW(1, a0.y); DOROW(2, a0.z); DOROW(3, a0.w);
            DOROW(4, a1.x); DOROW(5, a1.y); DOROW(6, a1.z); DOROW(7, a1.w);
#undef DOROW
        }
        if (kt < 127) {
            STORE_TILE(buf ^ 1);
            __syncthreads();
            buf ^= 1;
        }
    }

    // epilogue: +bias, exact GELU, store
    const int nbase = n0 + tx * 4;
    float4 bb0 = *(const float4*)&bias1[nbase];
    float4 bb1 = *(const float4*)&bias1[nbase + 64];
    float bv[8] = { bb0.x, bb0.y, bb0.z, bb0.w, bb1.x, bb1.y, bb1.z, bb1.w };
#pragma unroll
    for (int mi = 0; mi < 8; mi++) {
        int row = m0 + ty * 4 + (mi < 4 ? mi : 60 + mi);
        float* orow = g_h + (size_t)row * H2DIM;
#pragma unroll
        for (int nj = 0; nj < 4; nj++) {
            float lo = __uint_as_float((unsigned)(acc[mi][nj] & 0xFFFFFFFFull));
            float hi = __uint_as_float((unsigned)(acc[mi][nj] >> 32));
            int ncol = (nj < 2) ? (nbase + 2 * nj) : (nbase + 64 + 2 * (nj - 2));
            int bidx = (nj < 2) ? (2 * nj) : (4 + 2 * (nj - 2));
            float v0 = lo + bv[bidx];
            float v1 = hi + bv[bidx + 1];
            float g0 = 0.5f * v0 * (1.0f + erff(v0 * 0.7071067811865476f));
            float g1 = 0.5f * v1 * (1.0f + erff(v1 * 0.7071067811865476f));
            *(float2*)&orow[ncol] = make_float2(g0, g1);
        }
    }
#undef STORE_TILE
}

// ---------------- Kernel 3: zero expert sums ----------------
__global__ void zero_kernel()
{
    if (threadIdx.x < NEXP) g_sums[threadIdx.x] = 0.f;
}

// ---------------- Kernel 4: GEMM2 + routing epilogue ----------------
// One warp per token: logits = h @ w2^T + b2; ew=clip(logits/0.7,+-50);
// top-2 -> softmax -> masks (row-normalized); accumulate pre-norm sums.
__global__ __launch_bounds__(256)
void router_kernel(const float* __restrict__ w2,
                   const float* __restrict__ b2,
                   float* __restrict__ out_ew,
                   float* __restrict__ out_masks)
{
    __shared__ float w2s[NEXP][H2DIM];
    __shared__ float ssum[NEXP];
    int tid = threadIdx.x;
#pragma unroll
    for (int i = tid * 4; i < NEXP * H2DIM; i += 1024)
        *(float4*)&w2s[0][i] = *(const float4*)&w2[i];
    if (tid < NEXP) ssum[tid] = 0.f;
    __syncthreads();

    int warp = tid >> 5, lane = tid & 31;
    int token = blockIdx.x * 8 + warp;
    const float* hrow = g_h + (size_t)token * H2DIM;

    float acc[8] = {0, 0, 0, 0, 0, 0, 0, 0};
#pragma unroll
    for (int j = 0; j < 8; j++) {
        int k = lane * 4 + j * 128;
        float4 hv = *(const float4*)&hrow[k];
#pragma unroll
        for (int e = 0; e < 8; e++) {
            float4 wv = *(const float4*)&w2s[e][k];
            acc[e] = fmaf(hv.x, wv.x, fmaf(hv.y, wv.y,
                     fmaf(hv.z, wv.z, fmaf(hv.w, wv.w, acc[e]))));
        }
    }
#pragma unroll
    for (int off = 16; off; off >>= 1)
#pragma unroll
        for (int e = 0; e < 8; e++)
            acc[e] += __shfl_xor_sync(0xFFFFFFFFu, acc[e], off);

    if (lane == 0) {
        float ew[8];
#pragma unroll
        for (int e = 0; e < 8; e++) {
            float v = (acc[e] + b2[e]) / 0.7f;
            ew[e] = fminf(fmaxf(v, -50.f), 50.f);
        }
        float4* po = (float4*)(out_ew + (size_t)token * 8);
        po[0] = make_float4(ew[0], ew[1], ew[2], ew[3]);
        po[1] = make_float4(ew[4], ew[5], ew[6], ew[7]);

        // top-2, ties -> lower index (jax top_k semantics)
        int i0 = 0; float v0 = ew[0];
#pragma unroll
        for (int e = 1; e < 8; e++) if (ew[e] > v0) { v0 = ew[e]; i0 = e; }
        int i1 = -1; float v1 = -3.4e38f;
#pragma unroll
        for (int e = 0; e < 8; e++) if (e != i0 && ew[e] > v1) { v1 = ew[e]; i1 = e; }

        // softmax over (v0, v1), v0 is max
        float p1 = expf(v1 - v0);
        float s = 1.0f + p1;
        float sm0 = 1.0f / s;
        float sm1 = p1 / s;
        float rs = fmaxf(sm0 + sm1, 1e-6f);
        float mk[8] = {0, 0, 0, 0, 0, 0, 0, 0};
        mk[i0] = sm0 / rs;
        mk[i1] = sm1 / rs;
        float4* pm = (float4*)(out_masks + (size_t)token * 8);
        pm[0] = make_float4(mk[0], mk[1], mk[2], mk[3]);
        pm[1] = make_float4(mk[4], mk[5], mk[6], mk[7]);
        atomicAdd(&ssum[i0], sm0);   // pre-normalization weights feed count/usage
        atomicAdd(&ssum[i1], sm1);
    }
    __syncthreads();
    if (tid < NEXP) atomicAdd(&g_sums[tid], ssum[tid]);
}

// ---------------- Kernel 5: usage + KL loss ----------------
__global__ void finish_kernel(float* __restrict__ out_tail)
{
    if (threadIdx.x == 0) {
        float total = 0.f;
        float s[8];
#pragma unroll
        for (int e = 0; e < 8; e++) { s[e] = g_sums[e]; total += s[e]; }
        float den = fmaxf(total, 1e-6f);
        float kl = 0.f;
#pragma unroll
        for (int e = 0; e < 8; e++) {
            float u = s[e] / den;
            out_tail[1 + e] = u;
            kl += 0.125f * (logf(0.125f) - logf(fmaxf(u, 1e-6f)));
        }
        out_tail[0] = 0.01f * (kl * 0.125f);   // /num_experts (batchmean), *0.01
    }
}

// ---------------- launch ----------------
extern "C" void kernel_launch(void* const* d_in, const int* in_sizes, int n_in,
                              void* d_out, int out_size)
{
    const float* x   = (const float*)d_in[0];
    const float* lnw = (const float*)d_in[1];
    const float* lnb = (const float*)d_in[2];
    const float* w1  = (const float*)d_in[3];
    const float* b1  = (const float*)d_in[4];
    const float* w2  = (const float*)d_in[5];
    const float* b2  = (const float*)d_in[6];
    float* out = (float*)d_out;

    ln_stats_kernel<<<N_TOK / 8, 256>>>(x);
    gemm1_kernel<<<dim3(8, 256), 256>>>(x, lnw, lnb, w1, b1);
    zero_kernel<<<1, 32>>>();
    router_kernel<<<N_TOK / 8, 256>>>(w2, b2, out, out + (size_t)N_TOK * NEXP);
    finish_kernel<<<1, 32>>>(out + (size_t)2 * N_TOK * NEXP);
}

// round 8
// speedup vs baseline: 1.0568x; 1.0568x over previous
#include <cuda_runtime.h>
#include <cstdint>
#include <cstddef>

#define N_TOK 32768
#define HDIM  2048
#define H2DIM 1024
#define NEXP  8

// Scratch (no cudaMalloc allowed)
__device__ float g_h[(size_t)N_TOK * H2DIM];   // post-GELU hidden, 134 MB
__device__ float g_si[N_TOK];                  // rsqrt(var+eps)
__device__ float g_ti[N_TOK];                  // mu * rsqrt(var+eps)
__device__ float g_sums[NEXP];                 // per-expert weight sums

// ---------------- packed fp32x2 helpers (sm_100+) ----------------
#define PACK2(out, a) \
    asm("mov.b64 %0, {%1, %1};" : "=l"(out) : "r"(__float_as_uint(a)))
#define FMA2(d, a, b) \
    asm("fma.rn.f32x2 %0, %1, %2, %0;" : "+l"(d) : "l"(a), "l"(b))

// ---------------- Kernel 1: LayerNorm statistics ----------------
__global__ __launch_bounds__(256)
void ln_stats_kernel(const float* __restrict__ x)
{
    int warp = threadIdx.x >> 5, lane = threadIdx.x & 31;
    int token = blockIdx.x * 8 + warp;
    const float* row = x + (size_t)token * HDIM;
    float s = 0.f, sq = 0.f;
#pragma unroll
    for (int j = 0; j < 16; j++) {
        float4 v = *(const float4*)&row[lane * 4 + j * 128];
        s += v.x + v.y + v.z + v.w;
        sq = fmaf(v.x, v.x, fmaf(v.y, v.y, fmaf(v.z, v.z, fmaf(v.w, v.w, sq))));
    }
#pragma unroll
    for (int off = 16; off; off >>= 1) {
        s  += __shfl_xor_sync(0xFFFFFFFFu, s, off);
        sq += __shfl_xor_sync(0xFFFFFFFFu, sq, off);
    }
    if (lane == 0) {
        float mu  = s * (1.0f / 2048.0f);
        float var = sq * (1.0f / 2048.0f) - mu * mu;
        float v = var + 1e-5f;
        float r = rsqrtf(v);
        r = r * (1.5f - 0.5f * v * r * r);   // Newton refine -> ~IEEE accuracy
        g_si[token] = r;
        g_ti[token] = mu * r;
    }
}

// ---------------- Kernel 2: fused LN-apply + GEMM1 + bias + exact GELU ----------------
// C[m,n] = gelu( sum_k ((si[m]*x[m,k]-ti[m])*lnw[k]+lnb[k]) * w1[n,k] + b1[n] )
// Block tile 128x128, K-tile 16, 256 threads, 8x8 per-thread via fp32x2 pairs.
__global__ __launch_bounds__(256, 2)
void gemm1_kernel(const float* __restrict__ x,
                  const float* __restrict__ lnw,
                  const float* __restrict__ lnb,
                  const float* __restrict__ w1,
                  const float* __restrict__ bias1)
{
    __shared__ __align__(16) float As[2][16][132];
    __shared__ __align__(16) float Bs[2][16][132];

    const int tid = threadIdx.x;
    const int m0 = blockIdx.y * 128;
    const int n0 = blockIdx.x * 128;

    // loader mapping: thread owns float4 (r0, c4..c4+3) in rows r0 and r0+64
    const int r0 = tid >> 2;           // 0..63
    const int c4 = (tid & 3) << 2;     // 0,4,8,12

    const float si0 = g_si[m0 + r0];
    const float ti0 = g_ti[m0 + r0];
    const float si1 = g_si[m0 + r0 + 64];
    const float ti1 = g_ti[m0 + r0 + 64];

    const float* pA0 = x  + (size_t)(m0 + r0)      * HDIM + c4;
    const float* pA1 = x  + (size_t)(m0 + r0 + 64) * HDIM + c4;
    const float* pB0 = w1 + (size_t)(n0 + r0)      * HDIM + c4;
    const float* pB1 = w1 + (size_t)(n0 + r0 + 64) * HDIM + c4;

    const int tx = tid & 15;   // n quadrant
    const int ty = tid >> 4;   // m quadrant

    unsigned long long acc[8][4];
#pragma unroll
    for (int i = 0; i < 8; i++)
#pragma unroll
        for (int j = 0; j < 4; j++) acc[i][j] = 0ULL;

    float4 fa0, fa1, fb0, fb1, flw, flb;

#define STORE_TILE(bb) do { \
    As[bb][c4+0][r0]    = fmaf(flw.x, fmaf(si0, fa0.x, -ti0), flb.x); \
    As[bb][c4+1][r0]    = fmaf(flw.y, fmaf(si0, fa0.y, -ti0), flb.y); \
    As[bb][c4+2][r0]    = fmaf(flw.z, fmaf(si0, fa0.z, -ti0), flb.z); \
    As[bb][c4+3][r0]    = fmaf(flw.w, fmaf(si0, fa0.w, -ti0), flb.w); \
    As[bb][c4+0][r0+64] = fmaf(flw.x, fmaf(si1, fa1.x, -ti1), flb.x); \
    As[bb][c4+1][r0+64] = fmaf(flw.y, fmaf(si1, fa1.y, -ti1), flb.y); \
    As[bb][c4+2][r0+64] = fmaf(flw.z, fmaf(si1, fa1.z, -ti1), flb.z); \
    As[bb][c4+3][r0+64] = fmaf(flw.w, fmaf(si1, fa1.w, -ti1), flb.w); \
    Bs[bb][c4+0][r0]    = fb0.x; \
    Bs[bb][c4+1][r0]    = fb0.y; \
    Bs[bb][c4+2][r0]    = fb0.z; \
    Bs[bb][c4+3][r0]    = fb0.w; \
    Bs[bb][c4+0][r0+64] = fb1.x; \
    Bs[bb][c4+1][r0+64] = fb1.y; \
    Bs[bb][c4+2][r0+64] = fb1.z; \
    Bs[bb][c4+3][r0+64] = fb1.w; \
} while (0)

    // prologue: tile 0
    flw = *(const float4*)(lnw + c4);
    flb = *(const float4*)(lnb + c4);
    fa0 = *(const float4*)(pA0);
    fa1 = *(const float4*)(pA1);
    fb0 = *(const float4*)(pB0);
    fb1 = *(const float4*)(pB1);
    STORE_TILE(0);
    __syncthreads();

    int buf = 0;
#pragma unroll 1
    for (int kt = 0; kt < 128; kt++) {
        if (kt < 127) {
            const int k2 = (kt + 1) * 16;
            flw = *(const float4*)(lnw + k2 + c4);
            flb = *(const float4*)(lnb + k2 + c4);
            fa0 = *(const float4*)(pA0 + k2);
            fa1 = *(const float4*)(pA1 + k2);
            fb0 = *(const float4*)(pB0 + k2);
            fb1 = *(const float4*)(pB1 + k2);
        }
#pragma unroll
        for (int k = 0; k < 16; k++) {
            float4  a0  = *(const float4*)&As[buf][k][ty * 4];
            float4  a1  = *(const float4*)&As[buf][k][ty * 4 + 64];
            double2 bp0 = *(const double2*)&Bs[buf][k][tx * 4];
            double2 bp1 = *(const double2*)&Bs[buf][k][tx * 4 + 64];
            unsigned long long B0 = __double_as_longlong(bp0.x);
            unsigned long long B1 = __double_as_longlong(bp0.y);
            unsigned long long B2 = __double_as_longlong(bp1.x);
            unsigned long long B3 = __double_as_longlong(bp1.y);
#define DOROW(mi, aval) do { \
            unsigned long long Ad_; \
            PACK2(Ad_, aval); \
            FMA2(acc[mi][0], Ad_, B0); \
            FMA2(acc[mi][1], Ad_, B1); \
            FMA2(acc[mi][2], Ad_, B2); \
            FMA2(acc[mi][3], Ad_, B3); \
} while (0)
            DOROW(0, a0.x); DOROW(1, a0.y); DOROW(2, a0.z); DOROW(3, a0.w);
            DOROW(4, a1.x); DOROW(5, a1.y); DOROW(6, a1.z); DOROW(7, a1.w);
#undef DOROW
        }
        if (kt < 127) {
            STORE_TILE(buf ^ 1);
            __syncthreads();
            buf ^= 1;
        }
    }

    // epilogue: +bias, exact GELU, store
    const int nbase = n0 + tx * 4;
    float4 bb0 = *(const float4*)&bias1[nbase];
    float4 bb1 = *(const float4*)&bias1[nbase + 64];
    float bv[8] = { bb0.x, bb0.y, bb0.z, bb0.w, bb1.x, bb1.y, bb1.z, bb1.w };
#pragma unroll
    for (int mi = 0; mi < 8; mi++) {
        int row = m0 + ty * 4 + (mi < 4 ? mi : 60 + mi);
        float* orow = g_h + (size_t)row * H2DIM;
#pragma unroll
        for (int nj = 0; nj < 4; nj++) {
            float lo = __uint_as_float((unsigned)(acc[mi][nj] & 0xFFFFFFFFull));
            float hi = __uint_as_float((unsigned)(acc[mi][nj] >> 32));
            int ncol = (nj < 2) ? (nbase + 2 * nj) : (nbase + 64 + 2 * (nj - 2));
            int bidx = (nj < 2) ? (2 * nj) : (4 + 2 * (nj - 2));
            float v0 = lo + bv[bidx];
            float v1 = hi + bv[bidx + 1];
            float g0 = 0.5f * v0 * (1.0f + erff(v0 * 0.7071067811865476f));
            float g1 = 0.5f * v1 * (1.0f + erff(v1 * 0.7071067811865476f));
            *(float2*)&orow[ncol] = make_float2(g0, g1);
        }
    }
#undef STORE_TILE
}

// ---------------- Kernel 3: zero expert sums ----------------
__global__ void zero_kernel()
{
    if (threadIdx.x < NEXP) g_sums[threadIdx.x] = 0.f;
}

// ---------------- Kernel 4: GEMM2 + routing epilogue ----------------
// One warp per token: logits = h @ w2^T + b2; ew=clip(logits/0.7,+-50);
// top-2 -> softmax -> masks (row-normalized); accumulate pre-norm sums.
__global__ __launch_bounds__(256)
void router_kernel(const float* __restrict__ w2,
                   const float* __restrict__ b2,
                   float* __restrict__ out_ew,
                   float* __restrict__ out_masks)
{
    __shared__ float w2s[NEXP][H2DIM];
    __shared__ float ssum[NEXP];
    int tid = threadIdx.x;
#pragma unroll
    for (int i = tid * 4; i < NEXP * H2DIM; i += 1024)
        *(float4*)&w2s[0][i] = *(const float4*)&w2[i];
    if (tid < NEXP) ssum[tid] = 0.f;
    __syncthreads();

    int warp = tid >> 5, lane = tid & 31;
    int token = blockIdx.x * 8 + warp;
    const float* hrow = g_h + (size_t)token * H2DIM;

    float acc[8] = {0, 0, 0, 0, 0, 0, 0, 0};
#pragma unroll
    for (int j = 0; j < 8; j++) {
        int k = lane * 4 + j * 128;
        float4 hv = *(const float4*)&hrow[k];
#pragma unroll
        for (int e = 0; e < 8; e++) {
            float4 wv = *(const float4*)&w2s[e][k];
            acc[e] = fmaf(hv.x, wv.x, fmaf(hv.y, wv.y,
                     fmaf(hv.z, wv.z, fmaf(hv.w, wv.w, acc[e]))));
        }
    }
#pragma unroll
    for (int off = 16; off; off >>= 1)
#pragma unroll
        for (int e = 0; e < 8; e++)
            acc[e] += __shfl_xor_sync(0xFFFFFFFFu, acc[e], off);

    if (lane == 0) {
        float ew[8];
#pragma unroll
        for (int e = 0; e < 8; e++) {
            float v = (acc[e] + b2[e]) / 0.7f;
            ew[e] = fminf(fmaxf(v, -50.f), 50.f);
        }
        float4* po = (float4*)(out_ew + (size_t)token * 8);
        po[0] = make_float4(ew[0], ew[1], ew[2], ew[3]);
        po[1] = make_float4(ew[4], ew[5], ew[6], ew[7]);

        // top-2, ties -> lower index (jax top_k semantics)
        int i0 = 0; float v0 = ew[0];
#pragma unroll
        for (int e = 1; e < 8; e++) if (ew[e] > v0) { v0 = ew[e]; i0 = e; }
        int i1 = -1; float v1 = -3.4e38f;
#pragma unroll
        for (int e = 0; e < 8; e++) if (e != i0 && ew[e] > v1) { v1 = ew[e]; i1 = e; }

        // softmax over (v0, v1), v0 is max
        float p1 = expf(v1 - v0);
        float s = 1.0f + p1;
        float sm0 = 1.0f / s;
        float sm1 = p1 / s;
        float rs = fmaxf(sm0 + sm1, 1e-6f);
        float mk[8] = {0, 0, 0, 0, 0, 0, 0, 0};
        mk[i0] = sm0 / rs;
        mk[i1] = sm1 / rs;
        float4* pm = (float4*)(out_masks + (size_t)token * 8);
        pm[0] = make_float4(mk[0], mk[1], mk[2], mk[3]);
        pm[1] = make_float4(mk[4], mk[5], mk[6], mk[7]);
        atomicAdd(&ssum[i0], sm0);   // pre-normalization weights feed count/usage
        atomicAdd(&ssum[i1], sm1);
    }
    __syncthreads();
    if (tid < NEXP) atomicAdd(&g_sums[tid], ssum[tid]);
}

// ---------------- Kernel 5: usage + KL loss ----------------
__global__ void finish_kernel(float* __restrict__ out_tail)
{
    if (threadIdx.x == 0) {
        float total = 0.f;
        float s[8];
#pragma unroll
        for (int e = 0; e < 8; e++) { s[e] = g_sums[e]; total += s[e]; }
        float den = fmaxf(total, 1e-6f);
        float kl = 0.f;
#pragma unroll
        for (int e = 0; e < 8; e++) {
            float u = s[e] / den;
            out_tail[1 + e] = u;
            kl += 0.125f * (logf(0.125f) - logf(fmaxf(u, 1e-6f)));
        }
        out_tail[0] = 0.01f * (kl * 0.125f);   // /num_experts (batchmean), *0.01
    }
}

// ---------------- launch ----------------
extern "C" void kernel_launch(void* const* d_in, const int* in_sizes, int n_in,
                              void* d_out, int out_size)
{
    const float* x   = (const float*)d_in[0];
    const float* lnw = (const float*)d_in[1];
    const float* lnb = (const float*)d_in[2];
    const float* w1  = (const float*)d_in[3];
    const float* b1  = (const float*)d_in[4];
    const float* w2  = (const float*)d_in[5];
    const float* b2  = (const float*)d_in[6];
    float* out = (float*)d_out;

    ln_stats_kernel<<<N_TOK / 8, 256>>>(x);
    gemm1_kernel<<<dim3(8, 256), 256>>>(x, lnw, lnb, w1, b1);
    zero_kernel<<<1, 32>>>();
    router_kernel<<<N_TOK / 8, 256>>>(w2, b2, out, out + (size_t)N_TOK * NEXP);
    finish_kernel<<<1, 32>>>(out + (size_t)2 * N_TOK * NEXP);
}

// round 10
// speedup vs baseline: 1.1192x; 1.0590x over previous
#include <cuda_runtime.h>
#include <cuda_bf16.h>
#include <cstdint>
#include <cstddef>

#define N_TOK 32768
#define HDIM  2048
#define H2DIM 1024
#define NEXP  8

// ---------------- device scratch ----------------
__device__ float g_h[(size_t)N_TOK * H2DIM];
__device__ float g_si[N_TOK];
__device__ float g_ti[N_TOK];
__device__ float g_sums[NEXP];
// bf16 split levels, row-major [rows][2048]
__device__ __align__(16) __nv_bfloat16 g_A0[(size_t)N_TOK * HDIM];
__device__ __align__(16) __nv_bfloat16 g_A1[(size_t)N_TOK * HDIM];
__device__ __align__(16) __nv_bfloat16 g_A2[(size_t)N_TOK * HDIM];
__device__ __align__(16) __nv_bfloat16 g_B0[(size_t)H2DIM * HDIM];
__device__ __align__(16) __nv_bfloat16 g_B1[(size_t)H2DIM * HDIM];
__device__ __align__(16) __nv_bfloat16 g_B2[(size_t)H2DIM * HDIM];

__device__ __forceinline__ uint32_t smem_to_u32(const void* p) {
    uint32_t a;
    asm("{ .reg .u64 t; cvta.to.shared.u64 t, %1; cvt.u32.u64 %0, t; }" : "=r"(a) : "l"(p));
    return a;
}
#define CP_ASYNC16(dst, src) \
    asm volatile("cp.async.cg.shared.global [%0], [%1], 16;" :: "r"(dst), "l"(src) : "memory")
#define CP_COMMIT() asm volatile("cp.async.commit_group;" ::: "memory")
#define CP_WAIT1()  asm volatile("cp.async.wait_group 1;" ::: "memory")
#define LDSM_X4(r0, r1, r2, r3, addr) \
    asm volatile("ldmatrix.sync.aligned.m8n8.x4.shared.b16 {%0,%1,%2,%3}, [%4];" \
        : "=r"(r0), "=r"(r1), "=r"(r2), "=r"(r3) : "r"(addr))
#define MMA_BF16(c, a, b0, b1) \
    asm volatile("mma.sync.aligned.m16n8k16.row.col.f32.bf16.bf16.f32 " \
        "{%0,%1,%2,%3}, {%4,%5,%6,%7}, {%8,%9}, {%0,%1,%2,%3};" \
        : "+f"((c)[0]), "+f"((c)[1]), "+f"((c)[2]), "+f"((c)[3]) \
        : "r"((a)[0]), "r"((a)[1]), "r"((a)[2]), "r"((a)[3]), "r"(b0), "r"(b1))

// ---------------- K1: LayerNorm statistics ----------------
__global__ __launch_bounds__(256)
void ln_stats_kernel(const float* __restrict__ x)
{
    int warp = threadIdx.x >> 5, lane = threadIdx.x & 31;
    int token = blockIdx.x * 8 + warp;
    const float* row = x + (size_t)token * HDIM;
    float s = 0.f, sq = 0.f;
#pragma unroll
    for (int j = 0; j < 16; j++) {
        float4 v = *(const float4*)&row[lane * 4 + j * 128];
        s += v.x + v.y + v.z + v.w;
        sq = fmaf(v.x, v.x, fmaf(v.y, v.y, fmaf(v.z, v.z, fmaf(v.w, v.w, sq))));
    }
#pragma unroll
    for (int off = 16; off; off >>= 1) {
        s  += __shfl_xor_sync(0xFFFFFFFFu, s, off);
        sq += __shfl_xor_sync(0xFFFFFFFFu, sq, off);
    }
    if (lane == 0) {
        float mu  = s * (1.0f / 2048.0f);
        float var = sq * (1.0f / 2048.0f) - mu * mu;
        float v = var + 1e-5f;
        float r = rsqrtf(v);
        r = r * (1.5f - 0.5f * v * r * r);
        g_si[token] = r;
        g_ti[token] = mu * r;
    }
}

// ---------------- K2a: LN-apply + triple bf16 split of A ----------------
__global__ __launch_bounds__(256)
void a_convert_kernel(const float* __restrict__ x,
                      const float* __restrict__ lnw,
                      const float* __restrict__ lnb)
{
    int row = blockIdx.x;
    int k0  = threadIdx.x * 8;
    float si = g_si[row], ti = g_ti[row];
    const float* px = x + (size_t)row * HDIM + k0;
    float4 v0 = *(const float4*)px;
    float4 v1 = *(const float4*)(px + 4);
    float4 w0 = *(const float4*)(lnw + k0);
    float4 w1v = *(const float4*)(lnw + k0 + 4);
    float4 b0 = *(const float4*)(lnb + k0);
    float4 b1v = *(const float4*)(lnb + k0 + 4);
    float a[8] = {
        fmaf(w0.x,  fmaf(si, v0.x, -ti), b0.x),  fmaf(w0.y,  fmaf(si, v0.y, -ti), b0.y),
        fmaf(w0.z,  fmaf(si, v0.z, -ti), b0.z),  fmaf(w0.w,  fmaf(si, v0.w, -ti), b0.w),
        fmaf(w1v.x, fmaf(si, v1.x, -ti), b1v.x), fmaf(w1v.y, fmaf(si, v1.y, -ti), b1v.y),
        fmaf(w1v.z, fmaf(si, v1.z, -ti), b1v.z), fmaf(w1v.w, fmaf(si, v1.w, -ti), b1v.w)
    };
    __align__(16) __nv_bfloat16 hi[8], mid[8], lo[8];
#pragma unroll
    for (int j = 0; j < 8; j++) {
        __nv_bfloat16 h = __float2bfloat16(a[j]);
        float r1 = a[j] - __bfloat162float(h);
        __nv_bfloat16 m = __float2bfloat16(r1);
        float r2 = r1 - __bfloat162float(m);
        hi[j] = h; mid[j] = m; lo[j] = __float2bfloat16(r2);
    }
    size_t o = (size_t)row * HDIM + k0;
    *(uint4*)(g_A0 + o) = *(const uint4*)hi;
    *(uint4*)(g_A1 + o) = *(const uint4*)mid;
    *(uint4*)(g_A2 + o) = *(const uint4*)lo;
}

// ---------------- K2b: triple bf16 split of B = w1 ----------------
__global__ __launch_bounds__(256)
void b_convert_kernel(const float* __restrict__ w1)
{
    int row = blockIdx.x;
    int k0  = threadIdx.x * 8;
    const float* pw = w1 + (size_t)row * HDIM + k0;
    __align__(16) __nv_bfloat16 hi[8], mid[8], lo[8];
#pragma unroll
    for (int j = 0; j < 8; j++) {
        float a = pw[j];
        __nv_bfloat16 h = __float2bfloat16(a);
        float r1 = a - __bfloat162float(h);
        __nv_bfloat16 m = __float2bfloat16(r1);
        float r2 = r1 - __bfloat162float(m);
        hi[j] = h; mid[j] = m; lo[j] = __float2bfloat16(r2);
    }
    size_t o = (size_t)row * HDIM + k0;
    *(uint4*)(g_B0 + o) = *(const uint4*)hi;
    *(uint4*)(g_B1 + o) = *(const uint4*)mid;
    *(uint4*)(g_B2 + o) = *(const uint4*)lo;
}

// ---------------- K3: bf16x6 mma.sync GEMM + bias + exact GELU ----------------
// Block 128(m) x 256(n), BK=32 (2 k16 panels), 8 warps of 64x64.
// SMEM per stage: A lv: [2][128][24] bf16, B lv: [2][256][24]; x3 levels each.
#define PAD 24
#define A_LV_ELE (2 * 128 * PAD)                     // 6144
#define B_LV_ELE (2 * 256 * PAD)                     // 12288
#define STAGE_ELE (3 * A_LV_ELE + 3 * B_LV_ELE)      // 55296
#define STAGE_B (STAGE_ELE * 2)                      // 110592
#define SMEM_GEMM (2 * STAGE_B)                      // 221184

__global__ __launch_bounds__(256, 1)
void gemm1_mma_kernel(const float* __restrict__ bias1)
{
    extern __shared__ __align__(16) char smem[];
    const uint32_t sb = smem_to_u32(smem);
    const int tid = threadIdx.x, warp = tid >> 5, lane = tid & 31;
    const int m0 = blockIdx.y * 128;
    const int n0 = blockIdx.x * 256;
    const int m_off = (warp >> 2) * 64;     // 0 or 64
    const int n_off = (warp & 3) * 64;      // 0..192

    const __nv_bfloat16* gA[3] = { g_A0, g_A1, g_A2 };
    const __nv_bfloat16* gB[3] = { g_B0, g_B1, g_B2 };

    float acc[4][8][4];
#pragma unroll
    for (int mi = 0; mi < 4; mi++)
#pragma unroll
        for (int ni = 0; ni < 8; ni++)
#pragma unroll
            for (int q = 0; q < 4; q++) acc[mi][ni][q] = 0.f;

    // ---- stage loader: 4608 16B chunks (A: 1536, B: 3072) ----
#define LOAD_STAGE(buf, kt) do { \
    uint32_t sbase = sb + (buf) * STAGE_B; \
    int kb = (kt) * 32; \
    _Pragma("unroll") \
    for (int c = tid; c < 4608; c += 256) { \
        uint32_t dst; const __nv_bfloat16* src; \
        if (c < 1536) { \
            int l = c >> 9, rem = c & 511; \
            int pn = rem >> 8, r2 = rem & 255; \
            int row = r2 >> 1, ch = r2 & 1; \
            dst = sbase + (uint32_t)(l * A_LV_ELE + (pn * 128 + row) * PAD + ch * 8) * 2; \
            src = gA[l] + ((size_t)(m0 + row) * HDIM + kb + pn * 16 + ch * 8); \
        } else { \
            int c2 = c - 1536; \
            int l = c2 >> 10, rem = c2 & 1023; \
            int pn = rem >> 9, r2 = rem & 511; \
            int row = r2 >> 1, ch = r2 & 1; \
            dst = sbase + (uint32_t)(3 * A_LV_ELE + l * B_LV_ELE + (pn * 256 + row) * PAD + ch * 8) * 2; \
            src = gB[l] + ((size_t)(n0 + row) * HDIM + kb + pn * 16 + ch * 8); \
        } \
        CP_ASYNC16(dst, (const void*)src); \
    } \
} while (0)

    LOAD_STAGE(0, 0);
    CP_COMMIT();

#pragma unroll 1
    for (int kt = 0; kt < 64; kt++) {
        if (kt + 1 < 64) LOAD_STAGE((kt + 1) & 1, kt + 1);
        CP_COMMIT();
        CP_WAIT1();
        __syncthreads();

        const uint32_t stage = sb + (kt & 1) * STAGE_B;
#pragma unroll
        for (int p = 0; p < 2; p++) {
#pragma unroll
            for (int la = 0; la < 3; la++) {
                uint32_t aF[4][4];
#pragma unroll
                for (int mi = 0; mi < 4; mi++) {
                    uint32_t ad = stage + (uint32_t)(la * A_LV_ELE
                        + (p * 128 + m_off + mi * 16 + (lane & 15)) * PAD
                        + ((lane >> 4) & 1) * 8) * 2;
                    LDSM_X4(aF[mi][0], aF[mi][1], aF[mi][2], aF[mi][3], ad);
                }
#pragma unroll
                for (int lb = 0; lb < 3; lb++) {
                    if (la + lb > 2) continue;
                    uint32_t bF[4][4];
#pragma unroll
                    for (int ni2 = 0; ni2 < 4; ni2++) {
                        uint32_t bd = stage + (uint32_t)(3 * A_LV_ELE + lb * B_LV_ELE
                            + (p * 256 + n_off + ni2 * 16 + (lane & 7) + ((lane & 16) >> 1)) * PAD
                            + (lane & 8)) * 2;
                        LDSM_X4(bF[ni2][0], bF[ni2][1], bF[ni2][2], bF[ni2][3], bd);
                    }
#pragma unroll
                    for (int mi = 0; mi < 4; mi++)
#pragma unroll
                        for (int ni = 0; ni < 8; ni++) {
                            const uint32_t* bp = bF[ni >> 1];
                            if (ni & 1) MMA_BF16(acc[mi][ni], aF[mi], bp[2], bp[3]);
                            else        MMA_BF16(acc[mi][ni], aF[mi], bp[0], bp[1]);
                        }
                }
            }
        }
        __syncthreads();
    }

    // ---- epilogue: +bias, exact GELU, store fp32 ----
    const int lr = lane >> 2;
    const int lc = (lane & 3) * 2;
#pragma unroll
    for (int mi = 0; mi < 4; mi++) {
        int r_lo = m0 + m_off + mi * 16 + lr;
#pragma unroll
        for (int ni = 0; ni < 8; ni++) {
            int c = n0 + n_off + ni * 8 + lc;
            float2 bb = *(const float2*)&bias1[c];
            float v0 = acc[mi][ni][0] + bb.x;
            float v1 = acc[mi][ni][1] + bb.y;
            float v2 = acc[mi][ni][2] + bb.x;
            float v3 = acc[mi][ni][3] + bb.y;
            float2 o0, o1;
            o0.x = 0.5f * v0 * (1.0f + erff(v0 * 0.7071067811865476f));
            o0.y = 0.5f * v1 * (1.0f + erff(v1 * 0.7071067811865476f));
            o1.x = 0.5f * v2 * (1.0f + erff(v2 * 0.7071067811865476f));
            o1.y = 0.5f * v3 * (1.0f + erff(v3 * 0.7071067811865476f));
            *(float2*)&g_h[(size_t)r_lo * H2DIM + c] = o0;
            *(float2*)&g_h[(size_t)(r_lo + 8) * H2DIM + c] = o1;
        }
    }
}

// ---------------- K4: zero sums ----------------
__global__ void zero_kernel()
{
    if (threadIdx.x < NEXP) g_sums[threadIdx.x] = 0.f;
}

// ---------------- K5: GEMM2 + routing epilogue (proven) ----------------
__global__ __launch_bounds__(256)
void router_kernel(const float* __restrict__ w2,
                   const float* __restrict__ b2,
                   float* __restrict__ out_ew,
                   float* __restrict__ out_masks)
{
    __shared__ float w2s[NEXP][H2DIM];
    __shared__ float ssum[NEXP];
    int tid = threadIdx.x;
#pragma unroll
    for (int i = tid * 4; i < NEXP * H2DIM; i += 1024)
        *(float4*)&w2s[0][i] = *(const float4*)&w2[i];
    if (tid < NEXP) ssum[tid] = 0.f;
    __syncthreads();

    int warp = tid >> 5, lane = tid & 31;
    int token = blockIdx.x * 8 + warp;
    const float* hrow = g_h + (size_t)token * H2DIM;

    float acc[8] = {0, 0, 0, 0, 0, 0, 0, 0};
#pragma unroll
    for (int j = 0; j < 8; j++) {
        int k = lane * 4 + j * 128;
        float4 hv = *(const float4*)&hrow[k];
#pragma unroll
        for (int e = 0; e < 8; e++) {
            float4 wv = *(const float4*)&w2s[e][k];
            acc[e] = fmaf(hv.x, wv.x, fmaf(hv.y, wv.y, fmaf(hv.z, wv.z, fmaf(hv.w, wv.w, acc[e]))));
        }
    }
#pragma unroll
    for (int off = 16; off; off >>= 1)
#pragma unroll
        for (int e = 0; e < 8; e++)
            acc[e] += __shfl_xor_sync(0xFFFFFFFFu, acc[e], off);

    if (lane == 0) {
        float ew[8];
#pragma unroll
        for (int e = 0; e < 8; e++) {
            float v = (acc[e] + b2[e]) / 0.7f;
            ew[e] = fminf(fmaxf(v, -50.f), 50.f);
        }
        float4* po = (float4*)(out_ew + (size_t)token * 8);
        po[0] = make_float4(ew[0], ew[1], ew[2], ew[3]);
        po[1] = make_float4(ew[4], ew[5], ew[6], ew[7]);

        int i0 = 0; float v0 = ew[0];
#pragma unroll
        for (int e = 1; e < 8; e++) if (ew[e] > v0) { v0 = ew[e]; i0 = e; }
        int i1 = -1; float v1 = -3.4e38f;
#pragma unroll
        for (int e = 0; e < 8; e++) if (e != i0 && ew[e] > v1) { v1 = ew[e]; i1 = e; }

        float p1 = expf(v1 - v0);
        float s = 1.0f + p1;
        float sm0 = 1.0f / s;
        float sm1 = p1 / s;
        float rs = fmaxf(sm0 + sm1, 1e-6f);
        float mk[8] = {0, 0, 0, 0, 0, 0, 0, 0};
        mk[i0] = sm0 / rs;
        mk[i1] = sm1 / rs;
        float4* pm = (float4*)(out_masks + (size_t)token * 8);
        pm[0] = make_float4(mk[0], mk[1], mk[2], mk[3]);
        pm[1] = make_float4(mk[4], mk[5], mk[6], mk[7]);
        atomicAdd(&ssum[i0], sm0);
        atomicAdd(&ssum[i1], sm1);
    }
    __syncthreads();
    if (tid < NEXP) atomicAdd(&g_sums[tid], ssum[tid]);
}

// ---------------- K6: usage + KL ----------------
__global__ void finish_kernel(float* __restrict__ out_tail)
{
    if (threadIdx.x == 0) {
        float total = 0.f, s[8];
#pragma unroll
        for (int e = 0; e < 8; e++) { s[e] = g_sums[e]; total += s[e]; }
        float den = fmaxf(total, 1e-6f);
        float kl = 0.f;
#pragma unroll
        for (int e = 0; e < 8; e++) {
            float u = s[e] / den;
            out_tail[1 + e] = u;
            kl += 0.125f * (logf(0.125f) - logf(fmaxf(u, 1e-6f)));
        }
        out_tail[0] = 0.01f * (kl * 0.125f);
    }
}

// ---------------- launch ----------------
extern "C" void kernel_launch(void* const* d_in, const int* in_sizes, int n_in,
                              void* d_out, int out_size)
{
    const float* x   = (const float*)d_in[0];
    const float* lnw = (const float*)d_in[1];
    const float* lnb = (const float*)d_in[2];
    const float* w1  = (const float*)d_in[3];
    const float* b1  = (const float*)d_in[4];
    const float* w2  = (const float*)d_in[5];
    const float* b2  = (const float*)d_in[6];
    float* out = (float*)d_out;

    cudaFuncSetAttribute(gemm1_mma_kernel, cudaFuncAttributeMaxDynamicSharedMemorySize, SMEM_GEMM);

    ln_stats_kernel<<<N_TOK / 8, 256>>>(x);
    a_convert_kernel<<<N_TOK, 256>>>(x, lnw, lnb);
    b_convert_kernel<<<H2DIM, 256>>>(w1);
    gemm1_mma_kernel<<<dim3(4, 256), 256, SMEM_GEMM>>>(b1);
    zero_kernel<<<1, 32>>>();
    router_kernel<<<N_TOK / 8, 256>>>(w2, b2, out, out + (size_t)N_TOK * NEXP);
    finish_kernel<<<1, 32>>>(out + (size_t)2 * N_TOK * NEXP);
}

// round 12
// speedup vs baseline: 1.9039x; 1.7011x over previous
#include <cuda_runtime.h>
#include <cuda_fp16.h>
#include <cstdint>
#include <cstddef>

#define N_TOK 32768
#define HDIM  2048
#define H2DIM 1024
#define NEXP  8

// ---------------- device scratch ----------------
__device__ float g_h[(size_t)N_TOK * H2DIM];
__device__ float g_si[N_TOK];
__device__ float g_ti[N_TOK];
__device__ float g_sums[NEXP];
// fp16 split levels (hi, lo), row-major [rows][2048]
__device__ __align__(16) __half g_A0[(size_t)N_TOK * HDIM];
__device__ __align__(16) __half g_A1[(size_t)N_TOK * HDIM];
__device__ __align__(16) __half g_B0[(size_t)H2DIM * HDIM];
__device__ __align__(16) __half g_B1[(size_t)H2DIM * HDIM];

__device__ __forceinline__ uint32_t smem_to_u32(const void* p) {
    uint32_t a;
    asm("{ .reg .u64 t; cvta.to.shared.u64 t, %1; cvt.u32.u64 %0, t; }" : "=r"(a) : "l"(p));
    return a;
}
#define CP_ASYNC16(dst, src) \
    asm volatile("cp.async.cg.shared.global [%0], [%1], 16;" :: "r"(dst), "l"(src) : "memory")
#define CP_COMMIT() asm volatile("cp.async.commit_group;" ::: "memory")
#define CP_WAIT1()  asm volatile("cp.async.wait_group 1;" ::: "memory")
#define LDSM_X4(r0, r1, r2, r3, addr) \
    asm volatile("ldmatrix.sync.aligned.m8n8.x4.shared.b16 {%0,%1,%2,%3}, [%4];" \
        : "=r"(r0), "=r"(r1), "=r"(r2), "=r"(r3) : "r"(addr))
#define MMA_F16(c, a, b0, b1) \
    asm volatile("mma.sync.aligned.m16n8k16.row.col.f32.f16.f16.f32 " \
        "{%0,%1,%2,%3}, {%4,%5,%6,%7}, {%8,%9}, {%0,%1,%2,%3};" \
        : "+f"((c)[0]), "+f"((c)[1]), "+f"((c)[2]), "+f"((c)[3]) \
        : "r"((a)[0]), "r"((a)[1]), "r"((a)[2]), "r"((a)[3]), "r"(b0), "r"(b1))

// ---------------- K1: LayerNorm statistics ----------------
__global__ __launch_bounds__(256)
void ln_stats_kernel(const float* __restrict__ x)
{
    int warp = threadIdx.x >> 5, lane = threadIdx.x & 31;
    int token = blockIdx.x * 8 + warp;
    const float* row = x + (size_t)token * HDIM;
    float s = 0.f, sq = 0.f;
#pragma unroll
    for (int j = 0; j < 16; j++) {
        float4 v = *(const float4*)&row[lane * 4 + j * 128];
        s += v.x + v.y + v.z + v.w;
        sq = fmaf(v.x, v.x, fmaf(v.y, v.y, fmaf(v.z, v.z, fmaf(v.w, v.w, sq))));
    }
#pragma unroll
    for (int off = 16; off; off >>= 1) {
        s  += __shfl_xor_sync(0xFFFFFFFFu, s, off);
        sq += __shfl_xor_sync(0xFFFFFFFFu, sq, off);
    }
    if (lane == 0) {
        float mu  = s * (1.0f / 2048.0f);
        float var = sq * (1.0f / 2048.0f) - mu * mu;
        float v = var + 1e-5f;
        float r = rsqrtf(v);
        r = r * (1.5f - 0.5f * v * r * r);
        g_si[token] = r;
        g_ti[token] = mu * r;
    }
}

// ---------------- K2a: LN-apply + fp16 hi/lo split of A ----------------
__global__ __launch_bounds__(256)
void a_convert_kernel(const float* __restrict__ x,
                      const float* __restrict__ lnw,
                      const float* __restrict__ lnb)
{
    int row = blockIdx.x;
    int k0  = threadIdx.x * 8;
    float si = g_si[row], ti = g_ti[row];
    const float* px = x + (size_t)row * HDIM + k0;
    float4 v0 = *(const float4*)px;
    float4 v1 = *(const float4*)(px + 4);
    float4 w0 = *(const float4*)(lnw + k0);
    float4 w1v = *(const float4*)(lnw + k0 + 4);
    float4 b0 = *(const float4*)(lnb + k0);
    float4 b1v = *(const float4*)(lnb + k0 + 4);
    float a[8] = {
        fmaf(w0.x,  fmaf(si, v0.x, -ti), b0.x),  fmaf(w0.y,  fmaf(si, v0.y, -ti), b0.y),
        fmaf(w0.z,  fmaf(si, v0.z, -ti), b0.z),  fmaf(w0.w,  fmaf(si, v0.w, -ti), b0.w),
        fmaf(w1v.x, fmaf(si, v1.x, -ti), b1v.x), fmaf(w1v.y, fmaf(si, v1.y, -ti), b1v.y),
        fmaf(w1v.z, fmaf(si, v1.z, -ti), b1v.z), fmaf(w1v.w, fmaf(si, v1.w, -ti), b1v.w)
    };
    __align__(16) __half hi[8], lo[8];
#pragma unroll
    for (int j = 0; j < 8; j++) {
        __half h = __float2half_rn(a[j]);
        lo[j] = __float2half_rn(a[j] - __half2float(h));
        hi[j] = h;
    }
    size_t o = (size_t)row * HDIM + k0;
    *(uint4*)(g_A0 + o) = *(const uint4*)hi;
    *(uint4*)(g_A1 + o) = *(const uint4*)lo;
}

// ---------------- K2b: fp16 hi/lo split of B = w1 ----------------
__global__ __launch_bounds__(256)
void b_convert_kernel(const float* __restrict__ w1)
{
    int row = blockIdx.x;
    int k0  = threadIdx.x * 8;
    const float* pw = w1 + (size_t)row * HDIM + k0;
    __align__(16) __half hi[8], lo[8];
#pragma unroll
    for (int j = 0; j < 8; j++) {
        float a = pw[j];
        __half h = __float2half_rn(a);
        lo[j] = __float2half_rn(a - __half2float(h));
        hi[j] = h;
    }
    size_t o = (size_t)row * HDIM + k0;
    *(uint4*)(g_B0 + o) = *(const uint4*)hi;
    *(uint4*)(g_B1 + o) = *(const uint4*)lo;
}

// ---------------- K3: fp16x3 mma.sync GEMM + bias + exact GELU ----------------
// Block 128(m) x 256(n), BK=32 (2 k16 panels), 8 warps of 64x64, 3-stage cp.async.
#define PAD 24
#define A_LV_ELE (2 * 128 * PAD)                 // 6144
#define A_TOT    (2 * A_LV_ELE)                  // 12288
#define B_LV_ELE (2 * 256 * PAD)                 // 12288
#define STAGE_ELE (A_TOT + 2 * B_LV_ELE)         // 36864
#define STAGE_B  (STAGE_ELE * 2)                 // 73728
#define NST 3
#define SMEM_GEMM (NST * STAGE_B)                // 221184

__global__ __launch_bounds__(256, 1)
void gemm1_mma_kernel(const float* __restrict__ bias1)
{
    extern __shared__ __align__(16) char smem[];
    const uint32_t sb = smem_to_u32(smem);
    const int tid = threadIdx.x, warp = tid >> 5, lane = tid & 31;
    const int m0 = blockIdx.y * 128;
    const int n0 = blockIdx.x * 256;
    const int m_off = (warp >> 2) * 64;
    const int n_off = (warp & 3) * 64;

    const __half* gA[2] = { g_A0, g_A1 };
    const __half* gB[2] = { g_B0, g_B1 };

    float acc[4][8][4];
#pragma unroll
    for (int mi = 0; mi < 4; mi++)
#pragma unroll
        for (int ni = 0; ni < 8; ni++)
#pragma unroll
            for (int q = 0; q < 4; q++) acc[mi][ni][q] = 0.f;

    // 3072 16B chunks per stage (A: 1024, B: 2048), 12 per thread
#define LOAD_STAGE(buf, kt) do { \
    uint32_t sbase = sb + (buf) * STAGE_B; \
    int kb = (kt) * 32; \
    _Pragma("unroll") \
    for (int c = tid; c < 3072; c += 256) { \
        uint32_t dst; const __half* src; \
        if (c < 1024) { \
            int l = c >> 9, rem = c & 511; \
            int pn = rem >> 8, r2 = rem & 255; \
            int row = r2 >> 1, ch = r2 & 1; \
            dst = sbase + (uint32_t)(l * A_LV_ELE + (pn * 128 + row) * PAD + ch * 8) * 2; \
            src = gA[l] + ((size_t)(m0 + row) * HDIM + kb + pn * 16 + ch * 8); \
        } else { \
            int c2 = c - 1024; \
            int l = c2 >> 10, rem = c2 & 1023; \
            int pn = rem >> 9, r2 = rem & 511; \
            int row = r2 >> 1, ch = r2 & 1; \
            dst = sbase + (uint32_t)(A_TOT + l * B_LV_ELE + (pn * 256 + row) * PAD + ch * 8) * 2; \
            src = gB[l] + ((size_t)(n0 + row) * HDIM + kb + pn * 16 + ch * 8); \
        } \
        CP_ASYNC16(dst, (const void*)src); \
    } \
} while (0)

    LOAD_STAGE(0, 0); CP_COMMIT();
    LOAD_STAGE(1, 1); CP_COMMIT();

    int buf = 0, nbuf = 2;
#pragma unroll 1
    for (int kt = 0; kt < 64; kt++) {
        CP_WAIT1();
        __syncthreads();
        // top barrier proves buffer nbuf (= consumed at kt-1) is free for reuse
        if (kt + 2 < 64) LOAD_STAGE(nbuf, kt + 2);
        CP_COMMIT();

        const uint32_t stage = sb + buf * STAGE_B;
#pragma unroll
        for (int p = 0; p < 2; p++) {
            uint32_t aF[2][4][4];
#pragma unroll
            for (int l = 0; l < 2; l++)
#pragma unroll
                for (int mi = 0; mi < 4; mi++) {
                    uint32_t ad = stage + (uint32_t)(l * A_LV_ELE
                        + (p * 128 + m_off + mi * 16 + (lane & 15)) * PAD
                        + ((lane >> 4) & 1) * 8) * 2;
                    LDSM_X4(aF[l][mi][0], aF[l][mi][1], aF[l][mi][2], aF[l][mi][3], ad);
                }
            uint32_t bF[2][4][4];
#pragma unroll
            for (int l = 0; l < 2; l++)
#pragma unroll
                for (int ni2 = 0; ni2 < 4; ni2++) {
                    uint32_t bd = stage + (uint32_t)(A_TOT + l * B_LV_ELE
                        + (p * 256 + n_off + ni2 * 16 + (lane & 7) + ((lane & 16) >> 1)) * PAD
                        + (lane & 8)) * 2;
                    LDSM_X4(bF[l][ni2][0], bF[l][ni2][1], bF[l][ni2][2], bF[l][ni2][3], bd);
                }
            // passes: hi*hi, hi*lo, lo*hi
#pragma unroll
            for (int pass = 0; pass < 3; pass++) {
                const int la = (pass == 2) ? 1 : 0;
                const int lb = (pass == 1) ? 1 : 0;
#pragma unroll
                for (int mi = 0; mi < 4; mi++)
#pragma unroll
                    for (int ni = 0; ni < 8; ni++) {
                        const uint32_t* bp = bF[lb][ni >> 1];
                        if (ni & 1) MMA_F16(acc[mi][ni], aF[la][mi], bp[2], bp[3]);
                        else        MMA_F16(acc[mi][ni], aF[la][mi], bp[0], bp[1]);
                    }
            }
        }
        buf = (buf + 1) % NST;
        nbuf = (nbuf + 1) % NST;
    }

    // ---- epilogue: +bias, exact GELU, store fp32 ----
    const int lr = lane >> 2;
    const int lc = (lane & 3) * 2;
#pragma unroll
    for (int mi = 0; mi < 4; mi++) {
        int r_lo = m0 + m_off + mi * 16 + lr;
#pragma unroll
        for (int ni = 0; ni < 8; ni++) {
            int c = n0 + n_off + ni * 8 + lc;
            float2 bb = *(const float2*)&bias1[c];
            float v0 = acc[mi][ni][0] + bb.x;
            float v1 = acc[mi][ni][1] + bb.y;
            float v2 = acc[mi][ni][2] + bb.x;
            float v3 = acc[mi][ni][3] + bb.y;
            float2 o0, o1;
            o0.x = 0.5f * v0 * (1.0f + erff(v0 * 0.7071067811865476f));
            o0.y = 0.5f * v1 * (1.0f + erff(v1 * 0.7071067811865476f));
            o1.x = 0.5f * v2 * (1.0f + erff(v2 * 0.7071067811865476f));
            o1.y = 0.5f * v3 * (1.0f + erff(v3 * 0.7071067811865476f));
            *(float2*)&g_h[(size_t)r_lo * H2DIM + c] = o0;
            *(float2*)&g_h[(size_t)(r_lo + 8) * H2DIM + c] = o1;
        }
    }
}

// ---------------- K4: zero sums ----------------
__global__ void zero_kernel()
{
    if (threadIdx.x < NEXP) g_sums[threadIdx.x] = 0.f;
}

// ---------------- K5: GEMM2 + routing epilogue ----------------
__global__ __launch_bounds__(256)
void router_kernel(const float* __restrict__ w2,
                   const float* __restrict__ b2,
                   float* __restrict__ out_ew,
                   float* __restrict__ out_masks)
{
    __shared__ float w2s[NEXP][H2DIM];
    __shared__ float ssum[NEXP];
    int tid = threadIdx.x;
#pragma unroll
    for (int i = tid * 4; i < NEXP * H2DIM; i += 1024)
        *(float4*)&w2s[0][i] = *(const float4*)&w2[i];
    if (tid < NEXP) ssum[tid] = 0.f;
    __syncthreads();

    int warp = tid >> 5, lane = tid & 31;
    int token = blockIdx.x * 8 + warp;
    const float* hrow = g_h + (size_t)token * H2DIM;

    float acc[8] = {0, 0, 0, 0, 0, 0, 0, 0};
#pragma unroll
    for (int j = 0; j < 8; j++) {
        int k = lane * 4 + j * 128;
        float4 hv = *(const float4*)&hrow[k];
#pragma unroll
        for (int e = 0; e < 8; e++) {
            float4 wv = *(const float4*)&w2s[e][k];
            acc[e] = fmaf(hv.x, wv.x, fmaf(hv.y, wv.y, fmaf(hv.z, wv.z, fmaf(hv.w, wv.w, acc[e]))));
        }
    }
#pragma unroll
    for (int off = 16; off; off >>= 1)
#pragma unroll
        for (int e = 0; e < 8; e++)
            acc[e] += __shfl_xor_sync(0xFFFFFFFFu, acc[e], off);

    if (lane == 0) {
        float ew[8];
#pragma unroll
        for (int e = 0; e < 8; e++) {
            float v = (acc[e] + b2[e]) / 0.7f;
            ew[e] = fminf(fmaxf(v, -50.f), 50.f);
        }
        float4* po = (float4*)(out_ew + (size_t)token * 8);
        po[0] = make_float4(ew[0], ew[1], ew[2], ew[3]);
        po[1] = make_float4(ew[4], ew[5], ew[6], ew[7]);

        int i0 = 0; float v0 = ew[0];
#pragma unroll
        for (int e = 1; e < 8; e++) if (ew[e] > v0) { v0 = ew[e]; i0 = e; }
        int i1 = -1; float v1 = -3.4e38f;
#pragma unroll
        for (int e = 0; e < 8; e++) if (e != i0 && ew[e] > v1) { v1 = ew[e]; i1 = e; }

        float p1 = expf(v1 - v0);
        float s = 1.0f + p1;
        float sm0 = 1.0f / s;
        float sm1 = p1 / s;
        float rs = fmaxf(sm0 + sm1, 1e-6f);
        float mk[8] = {0, 0, 0, 0, 0, 0, 0, 0};
        mk[i0] = sm0 / rs;
        mk[i1] = sm1 / rs;
        float4* pm = (float4*)(out_masks + (size_t)token * 8);
        pm[0] = make_float4(mk[0], mk[1], mk[2], mk[3]);
        pm[1] = make_float4(mk[4], mk[5], mk[6], mk[7]);
        atomicAdd(&ssum[i0], sm0);
        atomicAdd(&ssum[i1], sm1);
    }
    __syncthreads();
    if (tid < NEXP) atomicAdd(&g_sums[tid], ssum[tid]);
}

// ---------------- K6: usage + KL ----------------
__global__ void finish_kernel(float* __restrict__ out_tail)
{
    if (threadIdx.x == 0) {
        float total = 0.f, s[8];
#pragma unroll
        for (int e = 0; e < 8; e++) { s[e] = g_sums[e]; total += s[e]; }
        float den = fmaxf(total, 1e-6f);
        float kl = 0.f;
#pragma unroll
        for (int e = 0; e < 8; e++) {
            float u = s[e] / den;
            out_tail[1 + e] = u;
            kl += 0.125f * (logf(0.125f) - logf(fmaxf(u, 1e-6f)));
        }
        out_tail[0] = 0.01f * (kl * 0.125f);
    }
}

// ---------------- launch ----------------
extern "C" void kernel_launch(void* const* d_in, const int* in_sizes, int n_in,
                              void* d_out, int out_size)
{
    const float* x   = (const float*)d_in[0];
    const float* lnw = (const float*)d_in[1];
    const float* lnb = (const float*)d_in[2];
    const float* w1  = (const float*)d_in[3];
    const float* b1  = (const float*)d_in[4];
    const float* w2  = (const float*)d_in[5];
    const float* b2  = (const float*)d_in[6];
    float* out = (float*)d_out;

    cudaFuncSetAttribute(gemm1_mma_kernel, cudaFuncAttributeMaxDynamicSharedMemorySize, SMEM_GEMM);

    ln_stats_kernel<<<N_TOK / 8, 256>>>(x);
    a_convert_kernel<<<N_TOK, 256>>>(x, lnw, lnb);
    b_convert_kernel<<<H2DIM, 256>>>(w1);
    gemm1_mma_kernel<<<dim3(4, 256), 256, SMEM_GEMM>>>(b1);
    zero_kernel<<<1, 32>>>();
    router_kernel<<<N_TOK / 8, 256>>>(w2, b2, out, out + (size_t)N_TOK * NEXP);
    finish_kernel<<<1, 32>>>(out + (size_t)2 * N_TOK * NEXP);
}

// round 14
// speedup vs baseline: 1.9813x; 1.0407x over previous
#include <cuda_runtime.h>
#include <cuda_fp16.h>
#include <cstdint>
#include <cstddef>

#define N_TOK 32768
#define HDIM  2048
#define H2DIM 1024
#define NEXP  8

// ---------------- device scratch ----------------
__device__ float g_h[(size_t)N_TOK * H2DIM];
__device__ float g_sums[NEXP];
// fp16 split levels (hi, lo), row-major [rows][2048]
__device__ __align__(16) __half g_A0[(size_t)N_TOK * HDIM];
__device__ __align__(16) __half g_A1[(size_t)N_TOK * HDIM];
__device__ __align__(16) __half g_B0[(size_t)H2DIM * HDIM];
__device__ __align__(16) __half g_B1[(size_t)H2DIM * HDIM];

__device__ __forceinline__ uint32_t smem_to_u32(const void* p) {
    uint32_t a;
    asm("{ .reg .u64 t; cvta.to.shared.u64 t, %1; cvt.u32.u64 %0, t; }" : "=r"(a) : "l"(p));
    return a;
}
#define CP_ASYNC16(dst, src) \
    asm volatile("cp.async.cg.shared.global [%0], [%1], 16;" :: "r"(dst), "l"(src) : "memory")
#define CP_COMMIT() asm volatile("cp.async.commit_group;" ::: "memory")
#define CP_WAIT1()  asm volatile("cp.async.wait_group 1;" ::: "memory")
#define LDSM_X4(r0, r1, r2, r3, addr) \
    asm volatile("ldmatrix.sync.aligned.m8n8.x4.shared.b16 {%0,%1,%2,%3}, [%4];" \
        : "=r"(r0), "=r"(r1), "=r"(r2), "=r"(r3) : "r"(addr))
#define MMA_F16(c, a, b0, b1) \
    asm volatile("mma.sync.aligned.m16n8k16.row.col.f32.f16.f16.f32 " \
        "{%0,%1,%2,%3}, {%4,%5,%6,%7}, {%8,%9}, {%0,%1,%2,%3};" \
        : "+f"((c)[0]), "+f"((c)[1]), "+f"((c)[2]), "+f"((c)[3]) \
        : "r"((a)[0]), "r"((a)[1]), "r"((a)[2]), "r"((a)[3]), "r"(b0), "r"(b1))

// ---------------- K1: fused LayerNorm + fp16 hi/lo split of A ----------------
// One block = one token row (256 threads x 8 elements = 2048).
__global__ __launch_bounds__(256)
void ln_a_convert_kernel(const float* __restrict__ x,
                         const float* __restrict__ lnw,
                         const float* __restrict__ lnb)
{
    __shared__ float red_s[8], red_q[8], bc[2];
    const int tid = threadIdx.x, warp = tid >> 5, lane = tid & 31;
    const int row = blockIdx.x;
    const int k0  = tid * 8;
    const float* px = x + (size_t)row * HDIM + k0;

    float4 v0 = *(const float4*)px;
    float4 v1 = *(const float4*)(px + 4);

    float s  = v0.x + v0.y + v0.z + v0.w + v1.x + v1.y + v1.z + v1.w;
    float sq = fmaf(v0.x, v0.x, fmaf(v0.y, v0.y, fmaf(v0.z, v0.z, fmaf(v0.w, v0.w,
               fmaf(v1.x, v1.x, fmaf(v1.y, v1.y, fmaf(v1.z, v1.z, v1.w * v1.w)))))));
#pragma unroll
    for (int off = 16; off; off >>= 1) {
        s  += __shfl_xor_sync(0xFFFFFFFFu, s, off);
        sq += __shfl_xor_sync(0xFFFFFFFFu, sq, off);
    }
    if (lane == 0) { red_s[warp] = s; red_q[warp] = sq; }
    __syncthreads();
    if (warp == 0) {
        float ts = (lane < 8) ? red_s[lane] : 0.f;
        float tq = (lane < 8) ? red_q[lane] : 0.f;
#pragma unroll
        for (int off = 4; off; off >>= 1) {
            ts += __shfl_xor_sync(0xFFFFFFFFu, ts, off);
            tq += __shfl_xor_sync(0xFFFFFFFFu, tq, off);
        }
        if (lane == 0) {
            float mu  = ts * (1.0f / 2048.0f);
            float var = tq * (1.0f / 2048.0f) - mu * mu;
            float v = var + 1e-5f;
            float r = rsqrtf(v);
            r = r * (1.5f - 0.5f * v * r * r);   // Newton -> ~IEEE rsqrt
            bc[0] = r;          // si
            bc[1] = mu * r;     // ti
        }
    }
    __syncthreads();
    const float si = bc[0], ti = bc[1];

    float4 w0 = *(const float4*)(lnw + k0);
    float4 w1v = *(const float4*)(lnw + k0 + 4);
    float4 b0 = *(const float4*)(lnb + k0);
    float4 b1v = *(const float4*)(lnb + k0 + 4);
    float a[8] = {
        fmaf(w0.x,  fmaf(si, v0.x, -ti), b0.x),  fmaf(w0.y,  fmaf(si, v0.y, -ti), b0.y),
        fmaf(w0.z,  fmaf(si, v0.z, -ti), b0.z),  fmaf(w0.w,  fmaf(si, v0.w, -ti), b0.w),
        fmaf(w1v.x, fmaf(si, v1.x, -ti), b1v.x), fmaf(w1v.y, fmaf(si, v1.y, -ti), b1v.y),
        fmaf(w1v.z, fmaf(si, v1.z, -ti), b1v.z), fmaf(w1v.w, fmaf(si, v1.w, -ti), b1v.w)
    };
    __align__(16) __half hi[8], lo[8];
#pragma unroll
    for (int j = 0; j < 8; j++) {
        __half h = __float2half_rn(a[j]);
        lo[j] = __float2half_rn(a[j] - __half2float(h));
        hi[j] = h;
    }
    size_t o = (size_t)row * HDIM + k0;
    *(uint4*)(g_A0 + o) = *(const uint4*)hi;
    *(uint4*)(g_A1 + o) = *(const uint4*)lo;
}

// ---------------- K2: fp16 hi/lo split of B = w1 ----------------
__global__ __launch_bounds__(256)
void b_convert_kernel(const float* __restrict__ w1)
{
    int row = blockIdx.x;
    int k0  = threadIdx.x * 8;
    const float* pw = w1 + (size_t)row * HDIM + k0;
    __align__(16) __half hi[8], lo[8];
#pragma unroll
    for (int j = 0; j < 8; j++) {
        float a = pw[j];
        __half h = __float2half_rn(a);
        lo[j] = __float2half_rn(a - __half2float(h));
        hi[j] = h;
    }
    size_t o = (size_t)row * HDIM + k0;
    *(uint4*)(g_B0 + o) = *(const uint4*)hi;
    *(uint4*)(g_B1 + o) = *(const uint4*)lo;
}

// ---------------- K3: fp16x3 mma.sync GEMM + bias + exact GELU ----------------
// Block 128(m) x 256(n), BK=32 (2 k16 panels), 8 warps of 64x64, 3-stage cp.async.
// Pass schedule per panel minimizes live fragments and interleaves LDSM with MMA:
//   LDSM(A_hi, B_hi) -> hi*hi ; LDSM(A_lo) -> lo*hi ; LDSM(B_lo) -> hi*lo
#define PAD 24
#define A_LV_ELE (2 * 128 * PAD)                 // 6144
#define A_TOT    (2 * A_LV_ELE)                  // 12288
#define B_LV_ELE (2 * 256 * PAD)                 // 12288
#define STAGE_ELE (A_TOT + 2 * B_LV_ELE)         // 36864
#define STAGE_B  (STAGE_ELE * 2)                 // 73728
#define NST 3
#define SMEM_GEMM (NST * STAGE_B)                // 221184

__global__ __launch_bounds__(256, 1)
void gemm1_mma_kernel(const float* __restrict__ bias1)
{
    extern __shared__ __align__(16) char smem[];
    const uint32_t sb = smem_to_u32(smem);
    const int tid = threadIdx.x, warp = tid >> 5, lane = tid & 31;
    const int m0 = blockIdx.y * 128;
    const int n0 = blockIdx.x * 256;
    const int m_off = (warp >> 2) * 64;
    const int n_off = (warp & 3) * 64;

    const __half* gA[2] = { g_A0, g_A1 };
    const __half* gB[2] = { g_B0, g_B1 };

    float acc[4][8][4];
#pragma unroll
    for (int mi = 0; mi < 4; mi++)
#pragma unroll
        for (int ni = 0; ni < 8; ni++)
#pragma unroll
            for (int q = 0; q < 4; q++) acc[mi][ni][q] = 0.f;

    // per-warp LDSM offsets (element units), relative to stage base
    const uint32_t a_off = (uint32_t)((m_off + (lane & 15)) * PAD + ((lane >> 4) & 1) * 8);
    const uint32_t b_off = (uint32_t)((n_off + (lane & 7) + ((lane & 16) >> 1)) * PAD + (lane & 8));

    // 3072 16B chunks per stage (A: 1024, B: 2048), 12 per thread
#define LOAD_STAGE(buf, kt) do { \
    uint32_t sbase = sb + (buf) * STAGE_B; \
    int kb = (kt) * 32; \
    _Pragma("unroll") \
    for (int c = tid; c < 3072; c += 256) { \
        uint32_t dst; const __half* src; \
        if (c < 1024) { \
            int l = c >> 9, rem = c & 511; \
            int pn = rem >> 8, r2 = rem & 255; \
            int row = r2 >> 1, ch = r2 & 1; \
            dst = sbase + (uint32_t)(l * A_LV_ELE + (pn * 128 + row) * PAD + ch * 8) * 2; \
            src = gA[l] + ((size_t)(m0 + row) * HDIM + kb + pn * 16 + ch * 8); \
        } else { \
            int c2 = c - 1024; \
            int l = c2 >> 10, rem = c2 & 1023; \
            int pn = rem >> 9, r2 = rem & 511; \
            int row = r2 >> 1, ch = r2 & 1; \
            dst = sbase + (uint32_t)(A_TOT + l * B_LV_ELE + (pn * 256 + row) * PAD + ch * 8) * 2; \
            src = gB[l] + ((size_t)(n0 + row) * HDIM + kb + pn * 16 + ch * 8); \
        } \
        CP_ASYNC16(dst, (const void*)src); \
    } \
} while (0)

#define DO_PASS(aF, bF) do { \
    _Pragma("unroll") \
    for (int mi = 0; mi < 4; mi++) \
        _Pragma("unroll") \
        for (int ni = 0; ni < 8; ni++) { \
            const uint32_t* bp = (bF)[ni >> 1]; \
            if (ni & 1) MMA_F16(acc[mi][ni], (aF)[mi], bp[2], bp[3]); \
            else        MMA_F16(acc[mi][ni], (aF)[mi], bp[0], bp[1]); \
        } \
} while (0)

    LOAD_STAGE(0, 0); CP_COMMIT();
    LOAD_STAGE(1, 1); CP_COMMIT();

    int buf = 0, nbuf = 2;
#pragma unroll 1
    for (int kt = 0; kt < 64; kt++) {
        CP_WAIT1();
        __syncthreads();
        if (kt + 2 < 64) LOAD_STAGE(nbuf, kt + 2);
        CP_COMMIT();

        const uint32_t stage = sb + buf * STAGE_B;
#pragma unroll
        for (int p = 0; p < 2; p++) {
            const uint32_t pa = stage + (uint32_t)(p * 128 * PAD + a_off) * 2;
            const uint32_t pb = stage + (uint32_t)(A_TOT * 2) + (uint32_t)(p * 256 * PAD + b_off) * 2;

            uint32_t aH[4][4], bH[4][4];
#pragma unroll
            for (int mi = 0; mi < 4; mi++)
                LDSM_X4(aH[mi][0], aH[mi][1], aH[mi][2], aH[mi][3],
                        pa + (uint32_t)(mi * 16 * PAD) * 2);
#pragma unroll
            for (int ni2 = 0; ni2 < 4; ni2++)
                LDSM_X4(bH[ni2][0], bH[ni2][1], bH[ni2][2], bH[ni2][3],
                        pb + (uint32_t)(ni2 * 16 * PAD) * 2);
            DO_PASS(aH, bH);                       // hi * hi

            uint32_t aL[4][4];
#pragma unroll
            for (int mi = 0; mi < 4; mi++)
                LDSM_X4(aL[mi][0], aL[mi][1], aL[mi][2], aL[mi][3],
                        pa + (uint32_t)(A_LV_ELE + mi * 16 * PAD) * 2);
            DO_PASS(aL, bH);                       // lo * hi  (B_hi reused)

            uint32_t bL[4][4];
#pragma unroll
            for (int ni2 = 0; ni2 < 4; ni2++)
                LDSM_X4(bL[ni2][0], bL[ni2][1], bL[ni2][2], bL[ni2][3],
                        pb + (uint32_t)(B_LV_ELE + ni2 * 16 * PAD) * 2);
            DO_PASS(aH, bL);                       // hi * lo  (A_hi reused)
        }
        buf = (buf + 1) % NST;
        nbuf = (nbuf + 1) % NST;
    }

    // ---- epilogue: +bias, exact GELU, store fp32 ----
    const int lr = lane >> 2;
    const int lc = (lane & 3) * 2;
#pragma unroll
    for (int mi = 0; mi < 4; mi++) {
        int r_lo = m0 + m_off + mi * 16 + lr;
#pragma unroll
        for (int ni = 0; ni < 8; ni++) {
            int c = n0 + n_off + ni * 8 + lc;
            float2 bb = *(const float2*)&bias1[c];
            float v0 = acc[mi][ni][0] + bb.x;
            float v1 = acc[mi][ni][1] + bb.y;
            float v2 = acc[mi][ni][2] + bb.x;
            float v3 = acc[mi][ni][3] + bb.y;
            float2 o0, o1;
            o0.x = 0.5f * v0 * (1.0f + erff(v0 * 0.7071067811865476f));
            o0.y = 0.5f * v1 * (1.0f + erff(v1 * 0.7071067811865476f));
            o1.x = 0.5f * v2 * (1.0f + erff(v2 * 0.7071067811865476f));
            o1.y = 0.5f * v3 * (1.0f + erff(v3 * 0.7071067811865476f));
            *(float2*)&g_h[(size_t)r_lo * H2DIM + c] = o0;
            *(float2*)&g_h[(size_t)(r_lo + 8) * H2DIM + c] = o1;
        }
    }
}

// ---------------- K4: zero sums ----------------
__global__ void zero_kernel()
{
    if (threadIdx.x < NEXP) g_sums[threadIdx.x] = 0.f;
}

// ---------------- K5: GEMM2 + routing epilogue ----------------
__global__ __launch_bounds__(256)
void router_kernel(const float* __restrict__ w2,
                   const float* __restrict__ b2,
                   float* __restrict__ out_ew,
                   float* __restrict__ out_masks)
{
    __shared__ float w2s[NEXP][H2DIM];
    __shared__ float ssum[NEXP];
    int tid = threadIdx.x;
#pragma unroll
    for (int i = tid * 4; i < NEXP * H2DIM; i += 1024)
        *(float4*)&w2s[0][i] = *(const float4*)&w2[i];
    if (tid < NEXP) ssum[tid] = 0.f;
    __syncthreads();

    int warp = tid >> 5, lane = tid & 31;
    int token = blockIdx.x * 8 + warp;
    const float* hrow = g_h + (size_t)token * H2DIM;

    float acc[8] = {0, 0, 0, 0, 0, 0, 0, 0};
#pragma unroll
    for (int j = 0; j < 8; j++) {
        int k = lane * 4 + j * 128;
        float4 hv = *(const float4*)&hrow[k];
#pragma unroll
        for (int e = 0; e < 8; e++) {
            float4 wv = *(const float4*)&w2s[e][k];
            acc[e] = fmaf(hv.x, wv.x, fmaf(hv.y, wv.y, fmaf(hv.z, wv.z, fmaf(hv.w, wv.w, acc[e]))));
        }
    }
#pragma unroll
    for (int off = 16; off; off >>= 1)
#pragma unroll
        for (int e = 0; e < 8; e++)
            acc[e] += __shfl_xor_sync(0xFFFFFFFFu, acc[e], off);

    if (lane == 0) {
        float ew[8];
#pragma unroll
        for (int e = 0; e < 8; e++) {
            float v = (acc[e] + b2[e]) / 0.7f;
            ew[e] = fminf(fmaxf(v, -50.f), 50.f);
        }
        float4* po = (float4*)(out_ew + (size_t)token * 8);
        po[0] = make_float4(ew[0], ew[1], ew[2], ew[3]);
        po[1] = make_float4(ew[4], ew[5], ew[6], ew[7]);

        int i0 = 0; float v0 = ew[0];
#pragma unroll
        for (int e = 1; e < 8; e++) if (ew[e] > v0) { v0 = ew[e]; i0 = e; }
        int i1 = -1; float v1 = -3.4e38f;
#pragma unroll
        for (int e = 0; e < 8; e++) if (e != i0 && ew[e] > v1) { v1 = ew[e]; i1 = e; }

        float p1 = expf(v1 - v0);
        float s = 1.0f + p1;
        float sm0 = 1.0f / s;
        float sm1 = p1 / s;
        float rs = fmaxf(sm0 + sm1, 1e-6f);
        float mk[8] = {0, 0, 0, 0, 0, 0, 0, 0};
        mk[i0] = sm0 / rs;
        mk[i1] = sm1 / rs;
        float4* pm = (float4*)(out_masks + (size_t)token * 8);
        pm[0] = make_float4(mk[0], mk[1], mk[2], mk[3]);
        pm[1] = make_float4(mk[4], mk[5], mk[6], mk[7]);
        atomicAdd(&ssum[i0], sm0);
        atomicAdd(&ssum[i1], sm1);
    }
    __syncthreads();
    if (tid < NEXP) atomicAdd(&g_sums[tid], ssum[tid]);
}

// ---------------- K6: usage + KL ----------------
__global__ void finish_kernel(float* __restrict__ out_tail)
{
    if (threadIdx.x == 0) {
        float total = 0.f, s[8];
#pragma unroll
        for (int e = 0; e < 8; e++) { s[e] = g_sums[e]; total += s[e]; }
        float den = fmaxf(total, 1e-6f);
        float kl = 0.f;
#pragma unroll
        for (int e = 0; e < 8; e++) {
            float u = s[e] / den;
            out_tail[1 + e] = u;
            kl += 0.125f * (logf(0.125f) - logf(fmaxf(u, 1e-6f)));
        }
        out_tail[0] = 0.01f * (kl * 0.125f);
    }
}

// ---------------- launch ----------------
extern "C" void kernel_launch(void* const* d_in, const int* in_sizes, int n_in,
                              void* d_out, int out_size)
{
    const float* x   = (const float*)d_in[0];
    const float* lnw = (const float*)d_in[1];
    const float* lnb = (const float*)d_in[2];
    const float* w1  = (const float*)d_in[3];
    const float* b1  = (const float*)d_in[4];
    const float* w2  = (const float*)d_in[5];
    const float* b2  = (const float*)d_in[6];
    float* out = (float*)d_out;

    cudaFuncSetAttribute(gemm1_mma_kernel, cudaFuncAttributeMaxDynamicSharedMemorySize, SMEM_GEMM);

    ln_a_convert_kernel<<<N_TOK, 256>>>(x, lnw, lnb);
    b_convert_kernel<<<H2DIM, 256>>>(w1);
    gemm1_mma_kernel<<<dim3(4, 256), 256, SMEM_GEMM>>>(b1);
    zero_kernel<<<1, 32>>>();
    router_kernel<<<N_TOK / 8, 256>>>(w2, b2, out, out + (size_t)N_TOK * NEXP);
    finish_kernel<<<1, 32>>>(out + (size_t)2 * N_TOK * NEXP);
}

// round 15
// speedup vs baseline: 2.2595x; 1.1404x over previous
#include <cuda_runtime.h>
#include <cuda_fp16.h>
#include <cstdint>
#include <cstddef>

#define N_TOK 32768
#define HDIM  2048
#define H2DIM 1024
#define NEXP  8

// ---------------- device scratch ----------------
__device__ float g_h[(size_t)N_TOK * H2DIM];
__device__ float g_sums[NEXP];
// fp16 split levels (hi, lo), row-major [rows][2048]
__device__ __align__(16) __half g_A0[(size_t)N_TOK * HDIM];
__device__ __align__(16) __half g_A1[(size_t)N_TOK * HDIM];
__device__ __align__(16) __half g_B0[(size_t)H2DIM * HDIM];
__device__ __align__(16) __half g_B1[(size_t)H2DIM * HDIM];

__device__ __forceinline__ uint32_t smem_to_u32(const void* p) {
    uint32_t a;
    asm("{ .reg .u64 t; cvta.to.shared.u64 t, %1; cvt.u32.u64 %0, t; }" : "=r"(a) : "l"(p));
    return a;
}
#define CP_ASYNC16(dst, src) \
    asm volatile("cp.async.cg.shared.global [%0], [%1], 16;" :: "r"(dst), "l"(src) : "memory")
#define CP_COMMIT() asm volatile("cp.async.commit_group;" ::: "memory")
#define CP_WAIT1()  asm volatile("cp.async.wait_group 1;" ::: "memory")
#define LDSM_X4(r0, r1, r2, r3, addr) \
    asm volatile("ldmatrix.sync.aligned.m8n8.x4.shared.b16 {%0,%1,%2,%3}, [%4];" \
        : "=r"(r0), "=r"(r1), "=r"(r2), "=r"(r3) : "r"(addr))
#define LDSM_X2(r0, r1, addr) \
    asm volatile("ldmatrix.sync.aligned.m8n8.x2.shared.b16 {%0,%1}, [%2];" \
        : "=r"(r0), "=r"(r1) : "r"(addr))
#define MMA_F16(c, a, b0, b1) \
    asm volatile("mma.sync.aligned.m16n8k16.row.col.f32.f16.f16.f32 " \
        "{%0,%1,%2,%3}, {%4,%5,%6,%7}, {%8,%9}, {%0,%1,%2,%3};" \
        : "+f"((c)[0]), "+f"((c)[1]), "+f"((c)[2]), "+f"((c)[3]) \
        : "r"((a)[0]), "r"((a)[1]), "r"((a)[2]), "r"((a)[3]), "r"(b0), "r"(b1))

// ---------------- K1: fused LayerNorm + fp16 hi/lo split of A ----------------
__global__ __launch_bounds__(256)
void ln_a_convert_kernel(const float* __restrict__ x,
                         const float* __restrict__ lnw,
                         const float* __restrict__ lnb)
{
    __shared__ float red_s[8], red_q[8], bc[2];
    const int tid = threadIdx.x, warp = tid >> 5, lane = tid & 31;
    const int row = blockIdx.x;
    const int k0  = tid * 8;
    const float* px = x + (size_t)row * HDIM + k0;

    float4 v0 = *(const float4*)px;
    float4 v1 = *(const float4*)(px + 4);

    float s  = v0.x + v0.y + v0.z + v0.w + v1.x + v1.y + v1.z + v1.w;
    float sq = fmaf(v0.x, v0.x, fmaf(v0.y, v0.y, fmaf(v0.z, v0.z, fmaf(v0.w, v0.w,
               fmaf(v1.x, v1.x, fmaf(v1.y, v1.y, fmaf(v1.z, v1.z, v1.w * v1.w)))))));
#pragma unroll
    for (int off = 16; off; off >>= 1) {
        s  += __shfl_xor_sync(0xFFFFFFFFu, s, off);
        sq += __shfl_xor_sync(0xFFFFFFFFu, sq, off);
    }
    if (lane == 0) { red_s[warp] = s; red_q[warp] = sq; }
    __syncthreads();
    if (warp == 0) {
        float ts = (lane < 8) ? red_s[lane] : 0.f;
        float tq = (lane < 8) ? red_q[lane] : 0.f;
#pragma unroll
        for (int off = 4; off; off >>= 1) {
            ts += __shfl_xor_sync(0xFFFFFFFFu, ts, off);
            tq += __shfl_xor_sync(0xFFFFFFFFu, tq, off);
        }
        if (lane == 0) {
            float mu  = ts * (1.0f / 2048.0f);
            float var = tq * (1.0f / 2048.0f) - mu * mu;
            float v = var + 1e-5f;
            float r = rsqrtf(v);
            r = r * (1.5f - 0.5f * v * r * r);
            bc[0] = r;
            bc[1] = mu * r;
        }
    }
    __syncthreads();
    const float si = bc[0], ti = bc[1];

    float4 w0 = *(const float4*)(lnw + k0);
    float4 w1v = *(const float4*)(lnw + k0 + 4);
    float4 b0 = *(const float4*)(lnb + k0);
    float4 b1v = *(const float4*)(lnb + k0 + 4);
    float a[8] = {
        fmaf(w0.x,  fmaf(si, v0.x, -ti), b0.x),  fmaf(w0.y,  fmaf(si, v0.y, -ti), b0.y),
        fmaf(w0.z,  fmaf(si, v0.z, -ti), b0.z),  fmaf(w0.w,  fmaf(si, v0.w, -ti), b0.w),
        fmaf(w1v.x, fmaf(si, v1.x, -ti), b1v.x), fmaf(w1v.y, fmaf(si, v1.y, -ti), b1v.y),
        fmaf(w1v.z, fmaf(si, v1.z, -ti), b1v.z), fmaf(w1v.w, fmaf(si, v1.w, -ti), b1v.w)
    };
    __align__(16) __half hi[8], lo[8];
#pragma unroll
    for (int j = 0; j < 8; j++) {
        __half h = __float2half_rn(a[j]);
        lo[j] = __float2half_rn(a[j] - __half2float(h));
        hi[j] = h;
    }
    size_t o = (size_t)row * HDIM + k0;
    *(uint4*)(g_A0 + o) = *(const uint4*)hi;
    *(uint4*)(g_A1 + o) = *(const uint4*)lo;
}

// ---------------- K2: fp16 hi/lo split of B = w1 (+ zero g_sums) ----------------
__global__ __launch_bounds__(256)
void b_convert_kernel(const float* __restrict__ w1)
{
    if (blockIdx.x == 0 && threadIdx.x < NEXP) g_sums[threadIdx.x] = 0.f;
    int row = blockIdx.x;
    int k0  = threadIdx.x * 8;
    const float* pw = w1 + (size_t)row * HDIM + k0;
    __align__(16) __half hi[8], lo[8];
#pragma unroll
    for (int j = 0; j < 8; j++) {
        float a = pw[j];
        __half h = __float2half_rn(a);
        lo[j] = __float2half_rn(a - __half2float(h));
        hi[j] = h;
    }
    size_t o = (size_t)row * HDIM + k0;
    *(uint4*)(g_B0 + o) = *(const uint4*)hi;
    *(uint4*)(g_B1 + o) = *(const uint4*)lo;
}

// ---------------- K3: fp16x3 mma.sync GEMM + bias + exact GELU ----------------
// Block 128(m) x 128(n), BK=32, 8 warps of 32x64, 3-stage cp.async, 2 CTAs/SM.
// SMEM tile layout: per row (0..127) one 128B line: k = lv*64 + panel*32 + chunk16,
// swizzled: addr = row*128 + (k ^ ((row&7)<<4)). Bank-conflict-free LDSM.
#define STAGE_B 32768          // A 16KB + B 16KB
#define B_ST    16384
#define NST     3
#define SMEM_GEMM (NST * STAGE_B)   // 98304 -> 2 CTAs/SM

__global__ __launch_bounds__(256, 2)
void gemm1_mma_kernel(const float* __restrict__ bias1)
{
    extern __shared__ __align__(128) char smem[];
    const uint32_t sb = smem_to_u32(smem);
    const int tid = threadIdx.x, warp = tid >> 5, lane = tid & 31;
    const int m0 = blockIdx.y * 128;
    const int n0 = blockIdx.x * 128;
    const int m_off = (warp >> 1) * 32;    // 0,32,64,96
    const int n_off = (warp & 1) * 64;     // 0,64

    const __half* gA[2] = { g_A0, g_A1 };
    const __half* gB[2] = { g_B0, g_B1 };

    float acc[2][8][4];
#pragma unroll
    for (int mi = 0; mi < 2; mi++)
#pragma unroll
        for (int ni = 0; ni < 8; ni++)
#pragma unroll
            for (int q = 0; q < 4; q++) acc[mi][ni][q] = 0.f;

    // 2048 16B chunks per stage (A: 1024, B: 1024), 8 per thread
#define LOAD_STAGE(buf, kt) do { \
    uint32_t sbase = sb + (buf) * STAGE_B; \
    int kb = (kt) * 32; \
    _Pragma("unroll") \
    for (int c = tid; c < 2048; c += 256) { \
        int half = c >> 10; \
        int c2 = c & 1023; \
        int lv = c2 >> 9, rem = c2 & 511; \
        int pn = rem >> 8, r2 = rem & 255; \
        int row = r2 >> 1, ch = r2 & 1; \
        int k = lv * 64 + pn * 32 + ch * 16; \
        uint32_t dst = sbase + half * B_ST \
                     + (uint32_t)(row * 128 + (k ^ ((row & 7) << 4))); \
        const __half* src = half \
            ? gB[lv] + ((size_t)(n0 + row) * HDIM + kb + pn * 16 + ch * 8) \
            : gA[lv] + ((size_t)(m0 + row) * HDIM + kb + pn * 16 + ch * 8); \
        CP_ASYNC16(dst, (const void*)src); \
    } \
} while (0)

#define DO_PASS(aF, bF) do { \
    _Pragma("unroll") \
    for (int mi = 0; mi < 2; mi++) \
        _Pragma("unroll") \
        for (int ni = 0; ni < 8; ni++) { \
            const uint32_t* bp = (bF)[ni >> 1]; \
            if (ni & 1) MMA_F16(acc[mi][ni], (aF)[mi], bp[2], bp[3]); \
            else        MMA_F16(acc[mi][ni], (aF)[mi], bp[0], bp[1]); \
        } \
} while (0)

    LOAD_STAGE(0, 0); CP_COMMIT();
    LOAD_STAGE(1, 1); CP_COMMIT();

    // per-lane components of LDSM addresses
    const int a_row_l = lane & 15;               // A: row within 16-row tile
    const int a_k_l   = (lane >> 4) * 16;        // A: 16B chunk within k16 piece
    const int b_row_l = (lane & 7) + ((lane >> 4) << 3);
    const int b_k_l   = (lane & 8) ? 16 : 0;

    int buf = 0, nbuf = 2;
#pragma unroll 1
    for (int kt = 0; kt < 64; kt++) {
        CP_WAIT1();
        __syncthreads();
        if (kt + 2 < 64) LOAD_STAGE(nbuf, kt + 2);
        CP_COMMIT();

        const uint32_t stage = sb + buf * STAGE_B;
#pragma unroll
        for (int p = 0; p < 2; p++) {
            uint32_t aH[2][4], bH[4][4];
#pragma unroll
            for (int mi = 0; mi < 2; mi++) {
                int row = m_off + mi * 16 + a_row_l;
                int k = p * 32 + a_k_l;                       // lv=0
                LDSM_X4(aH[mi][0], aH[mi][1], aH[mi][2], aH[mi][3],
                        stage + (uint32_t)(row * 128 + (k ^ ((row & 7) << 4))));
            }
#pragma unroll
            for (int ni2 = 0; ni2 < 4; ni2++) {
                int row = ni2 * 16 + n_off + b_row_l;
                int k = p * 32 + b_k_l;                       // lv=0
                LDSM_X4(bH[ni2][0], bH[ni2][1], bH[ni2][2], bH[ni2][3],
                        stage + B_ST + (uint32_t)(row * 128 + (k ^ ((row & 7) << 4))));
            }
            DO_PASS(aH, bH);                                  // hi * hi

            uint32_t aL[2][4];
#pragma unroll
            for (int mi = 0; mi < 2; mi++) {
                int row = m_off + mi * 16 + a_row_l;
                int k = 64 + p * 32 + a_k_l;                  // lv=1
                LDSM_X4(aL[mi][0], aL[mi][1], aL[mi][2], aL[mi][3],
                        stage + (uint32_t)(row * 128 + (k ^ ((row & 7) << 4))));
            }
            DO_PASS(aL, bH);                                  // lo * hi

            uint32_t bL[4][4];
#pragma unroll
            for (int ni2 = 0; ni2 < 4; ni2++) {
                int row = ni2 * 16 + n_off + b_row_l;
                int k = 64 + p * 32 + b_k_l;                  // lv=1
                LDSM_X4(bL[ni2][0], bL[ni2][1], bL[ni2][2], bL[ni2][3],
                        stage + B_ST + (uint32_t)(row * 128 + (k ^ ((row & 7) << 4))));
            }
            DO_PASS(aH, bL);                                  // hi * lo
        }
        buf = (buf + 1) % NST;
        nbuf = (nbuf + 1) % NST;
    }

    // ---- epilogue: +bias, exact GELU, store fp32 ----
    const int lr = lane >> 2;
    const int lc = (lane & 3) * 2;
#pragma unroll
    for (int mi = 0; mi < 2; mi++) {
        int r_lo = m0 + m_off + mi * 16 + lr;
#pragma unroll
        for (int ni = 0; ni < 8; ni++) {
            int c = n0 + n_off + ni * 8 + lc;
            float2 bb = *(const float2*)&bias1[c];
            float v0 = acc[mi][ni][0] + bb.x;
            float v1 = acc[mi][ni][1] + bb.y;
            float v2 = acc[mi][ni][2] + bb.x;
            float v3 = acc[mi][ni][3] + bb.y;
            float2 o0, o1;
            o0.x = 0.5f * v0 * (1.0f + erff(v0 * 0.7071067811865476f));
            o0.y = 0.5f * v1 * (1.0f + erff(v1 * 0.7071067811865476f));
            o1.x = 0.5f * v2 * (1.0f + erff(v2 * 0.7071067811865476f));
            o1.y = 0.5f * v3 * (1.0f + erff(v3 * 0.7071067811865476f));
            *(float2*)&g_h[(size_t)r_lo * H2DIM + c] = o0;
            *(float2*)&g_h[(size_t)(r_lo + 8) * H2DIM + c] = o1;
        }
    }
}

// ---------------- K4: GEMM2 + routing epilogue ----------------
__global__ __launch_bounds__(256)
void router_kernel(const float* __restrict__ w2,
                   const float* __restrict__ b2,
                   float* __restrict__ out_ew,
                   float* __restrict__ out_masks)
{
    __shared__ float w2s[NEXP][H2DIM];
    __shared__ float ssum[NEXP];
    int tid = threadIdx.x;
#pragma unroll
    for (int i = tid * 4; i < NEXP * H2DIM; i += 1024)
        *(float4*)&w2s[0][i] = *(const float4*)&w2[i];
    if (tid < NEXP) ssum[tid] = 0.f;
    __syncthreads();

    int warp = tid >> 5, lane = tid & 31;
    int token = blockIdx.x * 8 + warp;
    const float* hrow = g_h + (size_t)token * H2DIM;

    float acc[8] = {0, 0, 0, 0, 0, 0, 0, 0};
#pragma unroll
    for (int j = 0; j < 8; j++) {
        int k = lane * 4 + j * 128;
        float4 hv = *(const float4*)&hrow[k];
#pragma unroll
        for (int e = 0; e < 8; e++) {
            float4 wv = *(const float4*)&w2s[e][k];
            acc[e] = fmaf(hv.x, wv.x, fmaf(hv.y, wv.y, fmaf(hv.z, wv.z, fmaf(hv.w, wv.w, acc[e]))));
        }
    }
#pragma unroll
    for (int off = 16; off; off >>= 1)
#pragma unroll
        for (int e = 0; e < 8; e++)
            acc[e] += __shfl_xor_sync(0xFFFFFFFFu, acc[e], off);

    if (lane == 0) {
        float ew[8];
#pragma unroll
        for (int e = 0; e < 8; e++) {
            float v = (acc[e] + b2[e]) / 0.7f;
            ew[e] = fminf(fmaxf(v, -50.f), 50.f);
        }
        float4* po = (float4*)(out_ew + (size_t)token * 8);
        po[0] = make_float4(ew[0], ew[1], ew[2], ew[3]);
        po[1] = make_float4(ew[4], ew[5], ew[6], ew[7]);

        int i0 = 0; float v0 = ew[0];
#pragma unroll
        for (int e = 1; e < 8; e++) if (ew[e] > v0) { v0 = ew[e]; i0 = e; }
        int i1 = -1; float v1 = -3.4e38f;
#pragma unroll
        for (int e = 0; e < 8; e++) if (e != i0 && ew[e] > v1) { v1 = ew[e]; i1 = e; }

        float p1 = expf(v1 - v0);
        float s = 1.0f + p1;
        float sm0 = 1.0f / s;
        float sm1 = p1 / s;
        float rs = fmaxf(sm0 + sm1, 1e-6f);
        float mk[8] = {0, 0, 0, 0, 0, 0, 0, 0};
        mk[i0] = sm0 / rs;
        mk[i1] = sm1 / rs;
        float4* pm = (float4*)(out_masks + (size_t)token * 8);
        pm[0] = make_float4(mk[0], mk[1], mk[2], mk[3]);
        pm[1] = make_float4(mk[4], mk[5], mk[6], mk[7]);
        atomicAdd(&ssum[i0], sm0);
        atomicAdd(&ssum[i1], sm1);
    }
    __syncthreads();
    if (tid < NEXP) atomicAdd(&g_sums[tid], ssum[tid]);
}

// ---------------- K5: usage + KL ----------------
__global__ void finish_kernel(float* __restrict__ out_tail)
{
    if (threadIdx.x == 0) {
        float total = 0.f, s[8];
#pragma unroll
        for (int e = 0; e < 8; e++) { s[e] = g_sums[e]; total += s[e]; }
        float den = fmaxf(total, 1e-6f);
        float kl = 0.f;
#pragma unroll
        for (int e = 0; e < 8; e++) {
            float u = s[e] / den;
            out_tail[1 + e] = u;
            kl += 0.125f * (logf(0.125f) - logf(fmaxf(u, 1e-6f)));
        }
        out_tail[0] = 0.01f * (kl * 0.125f);
    }
}

// ---------------- launch ----------------
extern "C" void kernel_launch(void* const* d_in, const int* in_sizes, int n_in,
                              void* d_out, int out_size)
{
    const float* x   = (const float*)d_in[0];
    const float* lnw = (const float*)d_in[1];
    const float* lnb = (const float*)d_in[2];
    const float* w1  = (const float*)d_in[3];
    const float* b1  = (const float*)d_in[4];
    const float* w2  = (const float*)d_in[5];
    const float* b2  = (const float*)d_in[6];
    float* out = (float*)d_out;

    cudaFuncSetAttribute(gemm1_mma_kernel, cudaFuncAttributeMaxDynamicSharedMemorySize, SMEM_GEMM);

    ln_a_convert_kernel<<<N_TOK, 256>>>(x, lnw, lnb);
    b_convert_kernel<<<H2DIM, 256>>>(w1);
    gemm1_mma_kernel<<<dim3(8, 256), 256, SMEM_GEMM>>>(b1);
    router_kernel<<<N_TOK / 8, 256>>>(w2, b2, out, out + (size_t)N_TOK * NEXP);
    finish_kernel<<<1, 32>>>(out + (size_t)2 * N_TOK * NEXP);
}

// round 16
// speedup vs baseline: 2.9774x; 1.3177x over previous
#include <cuda_runtime.h>
#include <cuda_fp16.h>
#include <cstdint>
#include <cstddef>

#define N_TOK 32768
#define HDIM  2048
#define H2DIM 1024
#define NEXP  8

// ---------------- device scratch ----------------
__device__ float g_h[(size_t)N_TOK * H2DIM];
__device__ float g_sums[NEXP];
// fp16 split levels in pre-swizzled 8KB tiles:
// A: tile(mb 0..255, kc 0..63) at ((mb*64+kc)<<13); inside: r(0..127)*64 + swz-chunk
// B: tile(nb 0..7,   kc 0..63) at ((nb*64+kc)<<13)
__device__ __align__(16) __half g_A0[(size_t)N_TOK * HDIM];
__device__ __align__(16) __half g_A1[(size_t)N_TOK * HDIM];
__device__ __align__(16) __half g_B0[(size_t)H2DIM * HDIM];
__device__ __align__(16) __half g_B1[(size_t)H2DIM * HDIM];

__device__ __forceinline__ uint32_t smem_to_u32(const void* p) {
    uint32_t a;
    asm("{ .reg .u64 t; cvta.to.shared.u64 t, %1; cvt.u32.u64 %0, t; }" : "=r"(a) : "l"(p));
    return a;
}
#define MBAR_INIT(a, c) \
    asm volatile("mbarrier.init.shared.b64 [%0], %1;" :: "r"((uint32_t)(a)), "r"((uint32_t)(c)) : "memory")
#define MBAR_EXPECT_TX(a, tx) \
    asm volatile("mbarrier.arrive.expect_tx.shared.b64 _, [%0], %1;" :: "r"((uint32_t)(a)), "r"((uint32_t)(tx)) : "memory")
#define MBAR_WAIT_ACQ(mb, par) do { \
    uint32_t _m = (uint32_t)(mb), _p = (uint32_t)(par), _d; \
    asm volatile("{\n\t.reg .pred p;\n\tmbarrier.try_wait.parity.acquire.cta.shared::cta.b64 p, [%1], %2;\n\t" \
        "selp.b32 %0, 1, 0, p;\n\t}" : "=r"(_d) : "r"(_m), "r"(_p) : "memory"); \
    if (!_d) { \
        asm volatile("{\n\t.reg .pred P1;\n\tWL_%=:\n\t" \
            "mbarrier.try_wait.parity.acquire.cta.shared::cta.b64 P1, [%0], %1, 0x989680;\n\t" \
            "@P1 bra.uni WD_%=;\n\tbra.uni WL_%=;\n\tWD_%=:\n\t}" :: "r"(_m), "r"(_p) : "memory"); \
    } } while (0)
#define BULK_G2S(dst, src, bytes, mb) \
    asm volatile("cp.async.bulk.shared::cluster.global.mbarrier::complete_tx::bytes [%0], [%1], %2, [%3];" \
        :: "r"((uint32_t)(dst)), "l"((const void*)(src)), "r"((uint32_t)(bytes)), "r"((uint32_t)(mb)) : "memory")
#define FENCE_ASYNC() asm volatile("fence.proxy.async.shared::cta;" ::: "memory")
#define LDSM_X4(r0, r1, r2, r3, addr) \
    asm volatile("ldmatrix.sync.aligned.m8n8.x4.shared.b16 {%0,%1,%2,%3}, [%4];" \
        : "=r"(r0), "=r"(r1), "=r"(r2), "=r"(r3) : "r"(addr))
#define MMA_F16(c, a, b0, b1) \
    asm volatile("mma.sync.aligned.m16n8k16.row.col.f32.f16.f16.f32 " \
        "{%0,%1,%2,%3}, {%4,%5,%6,%7}, {%8,%9}, {%0,%1,%2,%3};" \
        : "+f"((c)[0]), "+f"((c)[1]), "+f"((c)[2]), "+f"((c)[3]) \
        : "r"((a)[0]), "r"((a)[1]), "r"((a)[2]), "r"((a)[3]), "r"(b0), "r"(b1))

// tile byte offset for (row-in-128, k-in-32) with chunk swizzle
__device__ __forceinline__ uint32_t tile_off(int r, int kbyte) {
    return (uint32_t)(r * 64 + (kbyte ^ (((r >> 1) & 3) << 4)));
}

// ---------------- K1: fused LayerNorm + fp16 hi/lo split of A (tiled out) ----------------
__global__ __launch_bounds__(256)
void ln_a_convert_kernel(const float* __restrict__ x,
                         const float* __restrict__ lnw,
                         const float* __restrict__ lnb)
{
    __shared__ float red_s[8], red_q[8], bc[2];
    const int tid = threadIdx.x, warp = tid >> 5, lane = tid & 31;
    const int row = blockIdx.x;
    const int k0  = tid * 8;
    const float* px = x + (size_t)row * HDIM + k0;

    float4 v0 = *(const float4*)px;
    float4 v1 = *(const float4*)(px + 4);

    float s  = v0.x + v0.y + v0.z + v0.w + v1.x + v1.y + v1.z + v1.w;
    float sq = fmaf(v0.x, v0.x, fmaf(v0.y, v0.y, fmaf(v0.z, v0.z, fmaf(v0.w, v0.w,
               fmaf(v1.x, v1.x, fmaf(v1.y, v1.y, fmaf(v1.z, v1.z, v1.w * v1.w)))))));
#pragma unroll
    for (int off = 16; off; off >>= 1) {
        s  += __shfl_xor_sync(0xFFFFFFFFu, s, off);
        sq += __shfl_xor_sync(0xFFFFFFFFu, sq, off);
    }
    if (lane == 0) { red_s[warp] = s; red_q[warp] = sq; }
    __syncthreads();
    if (warp == 0) {
        float ts = (lane < 8) ? red_s[lane] : 0.f;
        float tq = (lane < 8) ? red_q[lane] : 0.f;
#pragma unroll
        for (int off = 4; off; off >>= 1) {
            ts += __shfl_xor_sync(0xFFFFFFFFu, ts, off);
            tq += __shfl_xor_sync(0xFFFFFFFFu, tq, off);
        }
        if (lane == 0) {
            float mu  = ts * (1.0f / 2048.0f);
            float var = tq * (1.0f / 2048.0f) - mu * mu;
            float v = var + 1e-5f;
            float r = rsqrtf(v);
            r = r * (1.5f - 0.5f * v * r * r);
            bc[0] = r;
            bc[1] = mu * r;
        }
    }
    __syncthreads();
    const float si = bc[0], ti = bc[1];

    float4 w0 = *(const float4*)(lnw + k0);
    float4 w1v = *(const float4*)(lnw + k0 + 4);
    float4 b0 = *(const float4*)(lnb + k0);
    float4 b1v = *(const float4*)(lnb + k0 + 4);
    float a[8] = {
        fmaf(w0.x,  fmaf(si, v0.x, -ti), b0.x),  fmaf(w0.y,  fmaf(si, v0.y, -ti), b0.y),
        fmaf(w0.z,  fmaf(si, v0.z, -ti), b0.z),  fmaf(w0.w,  fmaf(si, v0.w, -ti), b0.w),
        fmaf(w1v.x, fmaf(si, v1.x, -ti), b1v.x), fmaf(w1v.y, fmaf(si, v1.y, -ti), b1v.y),
        fmaf(w1v.z, fmaf(si, v1.z, -ti), b1v.z), fmaf(w1v.w, fmaf(si, v1.w, -ti), b1v.w)
    };
    __align__(16) __half hi[8], lo[8];
#pragma unroll
    for (int j = 0; j < 8; j++) {
        __half h = __float2half_rn(a[j]);
        lo[j] = __float2half_rn(a[j] - __half2float(h));
        hi[j] = h;
    }
    // tiled + swizzled destination
    int mb = row >> 7, r = row & 127, kc = k0 >> 5;
    uint32_t cb = (uint32_t)(((k0 >> 3) & 3) << 4);
    size_t off = (((size_t)(mb * 64 + kc)) << 13) + tile_off(r, (int)cb);
    *(uint4*)((char*)g_A0 + off) = *(const uint4*)hi;
    *(uint4*)((char*)g_A1 + off) = *(const uint4*)lo;
}

// ---------------- K2: fp16 hi/lo split of B = w1 (tiled out, + zero g_sums) ----------------
__global__ __launch_bounds__(256)
void b_convert_kernel(const float* __restrict__ w1)
{
    if (blockIdx.x == 0 && threadIdx.x < NEXP) g_sums[threadIdx.x] = 0.f;
    int row = blockIdx.x;
    int k0  = threadIdx.x * 8;
    const float* pw = w1 + (size_t)row * HDIM + k0;
    __align__(16) __half hi[8], lo[8];
#pragma unroll
    for (int j = 0; j < 8; j++) {
        float a = pw[j];
        __half h = __float2half_rn(a);
        lo[j] = __float2half_rn(a - __half2float(h));
        hi[j] = h;
    }
    int nb = row >> 7, r = row & 127, kc = k0 >> 5;
    uint32_t cb = (uint32_t)(((k0 >> 3) & 3) << 4);
    size_t off = (((size_t)(nb * 64 + kc)) << 13) + tile_off(r, (int)cb);
    *(uint4*)((char*)g_B0 + off) = *(const uint4*)hi;
    *(uint4*)((char*)g_B1 + off) = *(const uint4*)lo;
}

// ---------------- K3: fp16x3 mma.sync GEMM, bulk-copy pipeline ----------------
// Block 128x128, BK=32, 8 warps 32x64, NST=3 x 32KB stages, 2 CTAs/SM.
// Stage: A_hi @0, A_lo @8K, B_hi @16K, B_lo @24K (each 128 rows x 64B, swizzled).
#define STAGE_B 32768
#define NST     3
#define SMEM_GEMM (NST * STAGE_B)   // 98304

__global__ __launch_bounds__(256, 2)
void gemm1_mma_kernel(const float* __restrict__ bias1)
{
    extern __shared__ __align__(128) char smem[];
    __shared__ __align__(8) uint64_t mbar[NST];
    const uint32_t sb = smem_to_u32(smem);
    const uint32_t mba = smem_to_u32(mbar);
    const int tid = threadIdx.x, warp = tid >> 5, lane = tid & 31;
    const int m0b = blockIdx.y;            // A tile row-block
    const int n0b = blockIdx.x;            // B tile row-block
    const int m_off = (warp >> 1) * 32;
    const int n_off = (warp & 1) * 64;

    float acc[2][8][4];
#pragma unroll
    for (int mi = 0; mi < 2; mi++)
#pragma unroll
        for (int ni = 0; ni < 8; ni++)
#pragma unroll
            for (int q = 0; q < 4; q++) acc[mi][ni][q] = 0.f;

#define ISSUE_STAGE(s, kt) do { \
    FENCE_ASYNC(); \
    uint32_t bar = mba + (s) * 8; \
    MBAR_EXPECT_TX(bar, STAGE_B); \
    uint32_t d = sb + (s) * STAGE_B; \
    size_t ta = ((size_t)(m0b * 64 + (kt))) << 13; \
    size_t tb = ((size_t)(n0b * 64 + (kt))) << 13; \
    BULK_G2S(d,         (const char*)g_A0 + ta, 8192, bar); \
    BULK_G2S(d + 8192,  (const char*)g_A1 + ta, 8192, bar); \
    BULK_G2S(d + 16384, (const char*)g_B0 + tb, 8192, bar); \
    BULK_G2S(d + 24576, (const char*)g_B1 + tb, 8192, bar); \
} while (0)

#define DO_PASS(aF, bF) do { \
    _Pragma("unroll") \
    for (int mi = 0; mi < 2; mi++) \
        _Pragma("unroll") \
        for (int ni = 0; ni < 8; ni++) { \
            const uint32_t* bp = (bF)[ni >> 1]; \
            if (ni & 1) MMA_F16(acc[mi][ni], (aF)[mi], bp[2], bp[3]); \
            else        MMA_F16(acc[mi][ni], (aF)[mi], bp[0], bp[1]); \
        } \
} while (0)

    if (tid == 0) {
#pragma unroll
        for (int s2 = 0; s2 < NST; s2++) MBAR_INIT(mba + s2 * 8, 1);
        FENCE_ASYNC();
    }
    __syncthreads();
    if (tid == 0) {
        ISSUE_STAGE(0, 0);
        ISSUE_STAGE(1, 1);
        ISSUE_STAGE(2, 2);
    }

    // per-lane LDSM address components
    const int a_row_l = lane & 15;
    const int a_k_l   = ((lane >> 4) & 1) * 16;
    const int b_row_l = (lane & 7) + ((lane >> 4) << 3);
    const int b_k_l   = (lane & 8) ? 16 : 0;

    int s = 0, ph = 0;
#pragma unroll 1
    for (int kt = 0; kt < 64; kt++) {
        MBAR_WAIT_ACQ(mba + s * 8, ph);
        const uint32_t stage = sb + s * STAGE_B;

#pragma unroll
        for (int p = 0; p < 2; p++) {
            uint32_t aH[2][4], bH[4][4];
#pragma unroll
            for (int mi = 0; mi < 2; mi++) {
                int row = m_off + mi * 16 + a_row_l;
                LDSM_X4(aH[mi][0], aH[mi][1], aH[mi][2], aH[mi][3],
                        stage + tile_off(row, p * 32 + a_k_l));
            }
#pragma unroll
            for (int ni2 = 0; ni2 < 4; ni2++) {
                int row = n_off + ni2 * 16 + b_row_l;
                LDSM_X4(bH[ni2][0], bH[ni2][1], bH[ni2][2], bH[ni2][3],
                        stage + 16384u + tile_off(row, p * 32 + b_k_l));
            }
            DO_PASS(aH, bH);                       // hi * hi

            uint32_t aL[2][4];
#pragma unroll
            for (int mi = 0; mi < 2; mi++) {
                int row = m_off + mi * 16 + a_row_l;
                LDSM_X4(aL[mi][0], aL[mi][1], aL[mi][2], aL[mi][3],
                        stage + 8192u + tile_off(row, p * 32 + a_k_l));
            }
            DO_PASS(aL, bH);                       // lo * hi

            uint32_t bL[4][4];
#pragma unroll
            for (int ni2 = 0; ni2 < 4; ni2++) {
                int row = n_off + ni2 * 16 + b_row_l;
                LDSM_X4(bL[ni2][0], bL[ni2][1], bL[ni2][2], bL[ni2][3],
                        stage + 24576u + tile_off(row, p * 32 + b_k_l));
            }
            DO_PASS(aH, bL);                       // hi * lo
        }

        __syncthreads();                           // all warps done reading stage s
        if (tid == 0 && kt + 3 < 64) ISSUE_STAGE(s, kt + 3);
        if (++s == NST) { s = 0; ph ^= 1; }
    }

    // ---- epilogue: +bias, exact GELU, store fp32 ----
    const int m0 = m0b * 128, n0 = n0b * 128;
    const int lr = lane >> 2;
    const int lc = (lane & 3) * 2;
#pragma unroll
    for (int mi = 0; mi < 2; mi++) {
        int r_lo = m0 + m_off + mi * 16 + lr;
#pragma unroll
        for (int ni = 0; ni < 8; ni++) {
            int c = n0 + n_off + ni * 8 + lc;
            float2 bb = *(const float2*)&bias1[c];
            float v0 = acc[mi][ni][0] + bb.x;
            float v1 = acc[mi][ni][1] + bb.y;
            float v2 = acc[mi][ni][2] + bb.x;
            float v3 = acc[mi][ni][3] + bb.y;
            float2 o0, o1;
            o0.x = 0.5f * v0 * (1.0f + erff(v0 * 0.7071067811865476f));
            o0.y = 0.5f * v1 * (1.0f + erff(v1 * 0.7071067811865476f));
            o1.x = 0.5f * v2 * (1.0f + erff(v2 * 0.7071067811865476f));
            o1.y = 0.5f * v3 * (1.0f + erff(v3 * 0.7071067811865476f));
            *(float2*)&g_h[(size_t)r_lo * H2DIM + c] = o0;
            *(float2*)&g_h[(size_t)(r_lo + 8) * H2DIM + c] = o1;
        }
    }
}

// ---------------- K4: GEMM2 + routing epilogue ----------------
__global__ __launch_bounds__(256)
void router_kernel(const float* __restrict__ w2,
                   const float* __restrict__ b2,
                   float* __restrict__ out_ew,
                   float* __restrict__ out_masks)
{
    __shared__ float w2s[NEXP][H2DIM];
    __shared__ float ssum[NEXP];
    int tid = threadIdx.x;
#pragma unroll
    for (int i = tid * 4; i < NEXP * H2DIM; i += 1024)
        *(float4*)&w2s[0][i] = *(const float4*)&w2[i];
    if (tid < NEXP) ssum[tid] = 0.f;
    __syncthreads();

    int warp = tid >> 5, lane = tid & 31;
    int token = blockIdx.x * 8 + warp;
    const float* hrow = g_h + (size_t)token * H2DIM;

    float acc[8] = {0, 0, 0, 0, 0, 0, 0, 0};
#pragma unroll
    for (int j = 0; j < 8; j++) {
        int k = lane * 4 + j * 128;
        float4 hv = *(const float4*)&hrow[k];
#pragma unroll
        for (int e = 0; e < 8; e++) {
            float4 wv = *(const float4*)&w2s[e][k];
            acc[e] = fmaf(hv.x, wv.x, fmaf(hv.y, wv.y, fmaf(hv.z, wv.z, fmaf(hv.w, wv.w, acc[e]))));
        }
    }
#pragma unroll
    for (int off = 16; off; off >>= 1)
#pragma unroll
        for (int e = 0; e < 8; e++)
            acc[e] += __shfl_xor_sync(0xFFFFFFFFu, acc[e], off);

    if (lane == 0) {
        float ew[8];
#pragma unroll
        for (int e = 0; e < 8; e++) {
            float v = (acc[e] + b2[e]) / 0.7f;
            ew[e] = fminf(fmaxf(v, -50.f), 50.f);
        }
        float4* po = (float4*)(out_ew + (size_t)token * 8);
        po[0] = make_float4(ew[0], ew[1], ew[2], ew[3]);
        po[1] = make_float4(ew[4], ew[5], ew[6], ew[7]);

        int i0 = 0; float v0 = ew[0];
#pragma unroll
        for (int e = 1; e < 8; e++) if (ew[e] > v0) { v0 = ew[e]; i0 = e; }
        int i1 = -1; float v1 = -3.4e38f;
#pragma unroll
        for (int e = 0; e < 8; e++) if (e != i0 && ew[e] > v1) { v1 = ew[e]; i1 = e; }

        float p1 = expf(v1 - v0);
        float sden = 1.0f + p1;
        float sm0 = 1.0f / sden;
        float sm1 = p1 / sden;
        float rs = fmaxf(sm0 + sm1, 1e-6f);
        float mk[8] = {0, 0, 0, 0, 0, 0, 0, 0};
        mk[i0] = sm0 / rs;
        mk[i1] = sm1 / rs;
        float4* pm = (float4*)(out_masks + (size_t)token * 8);
        pm[0] = make_float4(mk[0], mk[1], mk[2], mk[3]);
        pm[1] = make_float4(mk[4], mk[5], mk[6], mk[7]);
        atomicAdd(&ssum[i0], sm0);
        atomicAdd(&ssum[i1], sm1);
    }
    __syncthreads();
    if (tid < NEXP) atomicAdd(&g_sums[tid], ssum[tid]);
}

// ---------------- K5: usage + KL ----------------
__global__ void finish_kernel(float* __restrict__ out_tail)
{
    if (threadIdx.x == 0) {
        float total = 0.f, s[8];
#pragma unroll
        for (int e = 0; e < 8; e++) { s[e] = g_sums[e]; total += s[e]; }
        float den = fmaxf(total, 1e-6f);
        float kl = 0.f;
#pragma unroll
        for (int e = 0; e < 8; e++) {
            float u = s[e] / den;
            out_tail[1 + e] = u;
            kl += 0.125f * (logf(0.125f) - logf(fmaxf(u, 1e-6f)));
        }
        out_tail[0] = 0.01f * (kl * 0.125f);
    }
}

// ---------------- launch ----------------
extern "C" void kernel_launch(void* const* d_in, const int* in_sizes, int n_in,
                              void* d_out, int out_size)
{
    const float* x   = (const float*)d_in[0];
    const float* lnw = (const float*)d_in[1];
    const float* lnb = (const float*)d_in[2];
    const float* w1  = (const float*)d_in[3];
    const float* b1  = (const float*)d_in[4];
    const float* w2  = (const float*)d_in[5];
    const float* b2  = (const float*)d_in[6];
    float* out = (float*)d_out;

    cudaFuncSetAttribute(gemm1_mma_kernel, cudaFuncAttributeMaxDynamicSharedMemorySize, SMEM_GEMM);

    ln_a_convert_kernel<<<N_TOK, 256>>>(x, lnw, lnb);
    b_convert_kernel<<<H2DIM, 256>>>(w1);
    gemm1_mma_kernel<<<dim3(8, 256), 256, SMEM_GEMM>>>(b1);
    router_kernel<<<N_TOK / 8, 256>>>(w2, b2, out, out + (size_t)N_TOK * NEXP);
    finish_kernel<<<1, 32>>>(out + (size_t)2 * N_TOK * NEXP);
}

// round 17
// speedup vs baseline: 3.0128x; 1.0119x over previous
#include <cuda_runtime.h>
#include <cuda_fp16.h>
#include <cstdint>
#include <cstddef>

#define N_TOK 32768
#define HDIM  2048
#define H2DIM 1024
#define NEXP  8

// ---------------- device scratch ----------------
__device__ float g_h[(size_t)N_TOK * H2DIM];
__device__ float g_sums[NEXP];
// fp16 split levels in pre-swizzled 8KB tiles:
// A: tile(mb 0..255, kc 0..63) at ((mb*64+kc)<<13); inside: r(0..127)*64 + swz-chunk
// B: tile(nb 0..7,   kc 0..63) at ((nb*64+kc)<<13)
__device__ __align__(16) __half g_A0[(size_t)N_TOK * HDIM];
__device__ __align__(16) __half g_A1[(size_t)N_TOK * HDIM];
__device__ __align__(16) __half g_B0[(size_t)H2DIM * HDIM];
__device__ __align__(16) __half g_B1[(size_t)H2DIM * HDIM];

__device__ __forceinline__ uint32_t smem_to_u32(const void* p) {
    uint32_t a;
    asm("{ .reg .u64 t; cvta.to.shared.u64 t, %1; cvt.u32.u64 %0, t; }" : "=r"(a) : "l"(p));
    return a;
}
#define MBAR_INIT(a, c) \
    asm volatile("mbarrier.init.shared.b64 [%0], %1;" :: "r"((uint32_t)(a)), "r"((uint32_t)(c)) : "memory")
#define MBAR_EXPECT_TX(a, tx) \
    asm volatile("mbarrier.arrive.expect_tx.shared.b64 _, [%0], %1;" :: "r"((uint32_t)(a)), "r"((uint32_t)(tx)) : "memory")
#define MBAR_WAIT_ACQ(mb, par) do { \
    uint32_t _m = (uint32_t)(mb), _p = (uint32_t)(par), _d; \
    asm volatile("{\n\t.reg .pred p;\n\tmbarrier.try_wait.parity.acquire.cta.shared::cta.b64 p, [%1], %2;\n\t" \
        "selp.b32 %0, 1, 0, p;\n\t}" : "=r"(_d) : "r"(_m), "r"(_p) : "memory"); \
    if (!_d) { \
        asm volatile("{\n\t.reg .pred P1;\n\tWL_%=:\n\t" \
            "mbarrier.try_wait.parity.acquire.cta.shared::cta.b64 P1, [%0], %1, 0x989680;\n\t" \
            "@P1 bra.uni WD_%=;\n\tbra.uni WL_%=;\n\tWD_%=:\n\t}" :: "r"(_m), "r"(_p) : "memory"); \
    } } while (0)
#define BULK_G2S(dst, src, bytes, mb) \
    asm volatile("cp.async.bulk.shared::cluster.global.mbarrier::complete_tx::bytes [%0], [%1], %2, [%3];" \
        :: "r"((uint32_t)(dst)), "l"((const void*)(src)), "r"((uint32_t)(bytes)), "r"((uint32_t)(mb)) : "memory")
#define FENCE_ASYNC() asm volatile("fence.proxy.async.shared::cta;" ::: "memory")
#define LDSM_X4(r0, r1, r2, r3, addr) \
    asm volatile("ldmatrix.sync.aligned.m8n8.x4.shared.b16 {%0,%1,%2,%3}, [%4];" \
        : "=r"(r0), "=r"(r1), "=r"(r2), "=r"(r3) : "r"(addr))
#define MMA_F16(c, a, b0, b1) \
    asm volatile("mma.sync.aligned.m16n8k16.row.col.f32.f16.f16.f32 " \
        "{%0,%1,%2,%3}, {%4,%5,%6,%7}, {%8,%9}, {%0,%1,%2,%3};" \
        : "+f"((c)[0]), "+f"((c)[1]), "+f"((c)[2]), "+f"((c)[3]) \
        : "r"((a)[0]), "r"((a)[1]), "r"((a)[2]), "r"((a)[3]), "r"(b0), "r"(b1))

// tile byte offset for (row-in-128, k-in-32) with chunk swizzle
__device__ __forceinline__ uint32_t tile_off(int r, int kbyte) {
    return (uint32_t)(r * 64 + (kbyte ^ (((r >> 1) & 3) << 4)));
}

// ---------------- K1: fused LayerNorm + fp16 hi/lo split of A (tiled out) ----------------
__global__ __launch_bounds__(256)
void ln_a_convert_kernel(const float* __restrict__ x,
                         const float* __restrict__ lnw,
                         const float* __restrict__ lnb)
{
    __shared__ float red_s[8], red_q[8], bc[2];
    const int tid = threadIdx.x, warp = tid >> 5, lane = tid & 31;
    const int row = blockIdx.x;
    const int k0  = tid * 8;
    const float* px = x + (size_t)row * HDIM + k0;

    float4 v0 = *(const float4*)px;
    float4 v1 = *(const float4*)(px + 4);

    float s  = v0.x + v0.y + v0.z + v0.w + v1.x + v1.y + v1.z + v1.w;
    float sq = fmaf(v0.x, v0.x, fmaf(v0.y, v0.y, fmaf(v0.z, v0.z, fmaf(v0.w, v0.w,
               fmaf(v1.x, v1.x, fmaf(v1.y, v1.y, fmaf(v1.z, v1.z, v1.w * v1.w)))))));
#pragma unroll
    for (int off = 16; off; off >>= 1) {
        s  += __shfl_xor_sync(0xFFFFFFFFu, s, off);
        sq += __shfl_xor_sync(0xFFFFFFFFu, sq, off);
    }
    if (lane == 0) { red_s[warp] = s; red_q[warp] = sq; }
    __syncthreads();
    if (warp == 0) {
        float ts = (lane < 8) ? red_s[lane] : 0.f;
        float tq = (lane < 8) ? red_q[lane] : 0.f;
#pragma unroll
        for (int off = 4; off; off >>= 1) {
            ts += __shfl_xor_sync(0xFFFFFFFFu, ts, off);
            tq += __shfl_xor_sync(0xFFFFFFFFu, tq, off);
        }
        if (lane == 0) {
            float mu  = ts * (1.0f / 2048.0f);
            float var = tq * (1.0f / 2048.0f) - mu * mu;
            float v = var + 1e-5f;
            float r = rsqrtf(v);
            r = r * (1.5f - 0.5f * v * r * r);
            bc[0] = r;
            bc[1] = mu * r;
        }
    }
    __syncthreads();
    const float si = bc[0], ti = bc[1];

    float4 w0 = *(const float4*)(lnw + k0);
    float4 w1v = *(const float4*)(lnw + k0 + 4);
    float4 b0 = *(const float4*)(lnb + k0);
    float4 b1v = *(const float4*)(lnb + k0 + 4);
    float a[8] = {
        fmaf(w0.x,  fmaf(si, v0.x, -ti), b0.x),  fmaf(w0.y,  fmaf(si, v0.y, -ti), b0.y),
        fmaf(w0.z,  fmaf(si, v0.z, -ti), b0.z),  fmaf(w0.w,  fmaf(si, v0.w, -ti), b0.w),
        fmaf(w1v.x, fmaf(si, v1.x, -ti), b1v.x), fmaf(w1v.y, fmaf(si, v1.y, -ti), b1v.y),
        fmaf(w1v.z, fmaf(si, v1.z, -ti), b1v.z), fmaf(w1v.w, fmaf(si, v1.w, -ti), b1v.w)
    };
    __align__(16) __half hi[8], lo[8];
#pragma unroll
    for (int j = 0; j < 8; j++) {
        __half h = __float2half_rn(a[j]);
        lo[j] = __float2half_rn(a[j] - __half2float(h));
        hi[j] = h;
    }
    int mb = row >> 7, r = row & 127, kc = k0 >> 5;
    uint32_t cb = (uint32_t)(((k0 >> 3) & 3) << 4);
    size_t off = (((size_t)(mb * 64 + kc)) << 13) + tile_off(r, (int)cb);
    *(uint4*)((char*)g_A0 + off) = *(const uint4*)hi;
    *(uint4*)((char*)g_A1 + off) = *(const uint4*)lo;
}

// ---------------- K2: fp16 hi/lo split of B = w1 (tiled out, + zero g_sums) ----------------
__global__ __launch_bounds__(256)
void b_convert_kernel(const float* __restrict__ w1)
{
    if (blockIdx.x == 0 && threadIdx.x < NEXP) g_sums[threadIdx.x] = 0.f;
    int row = blockIdx.x;
    int k0  = threadIdx.x * 8;
    const float* pw = w1 + (size_t)row * HDIM + k0;
    __align__(16) __half hi[8], lo[8];
#pragma unroll
    for (int j = 0; j < 8; j++) {
        float a = pw[j];
        __half h = __float2half_rn(a);
        lo[j] = __float2half_rn(a - __half2float(h));
        hi[j] = h;
    }
    int nb = row >> 7, r = row & 127, kc = k0 >> 5;
    uint32_t cb = (uint32_t)(((k0 >> 3) & 3) << 4);
    size_t off = (((size_t)(nb * 64 + kc)) << 13) + tile_off(r, (int)cb);
    *(uint4*)((char*)g_B0 + off) = *(const uint4*)hi;
    *(uint4*)((char*)g_B1 + off) = *(const uint4*)lo;
}

// ---------------- K3: fp16x3 mma.sync GEMM, bulk-copy pipeline (unchanged) ----------------
#define STAGE_B 32768
#define NST     3
#define SMEM_GEMM (NST * STAGE_B)   // 98304

__global__ __launch_bounds__(256, 2)
void gemm1_mma_kernel(const float* __restrict__ bias1)
{
    extern __shared__ __align__(128) char smem[];
    __shared__ __align__(8) uint64_t mbar[NST];
    const uint32_t sb = smem_to_u32(smem);
    const uint32_t mba = smem_to_u32(mbar);
    const int tid = threadIdx.x, warp = tid >> 5, lane = tid & 31;
    const int m0b = blockIdx.y;
    const int n0b = blockIdx.x;
    const int m_off = (warp >> 1) * 32;
    const int n_off = (warp & 1) * 64;

    float acc[2][8][4];
#pragma unroll
    for (int mi = 0; mi < 2; mi++)
#pragma unroll
        for (int ni = 0; ni < 8; ni++)
#pragma unroll
            for (int q = 0; q < 4; q++) acc[mi][ni][q] = 0.f;

#define ISSUE_STAGE(s, kt) do { \
    FENCE_ASYNC(); \
    uint32_t bar = mba + (s) * 8; \
    MBAR_EXPECT_TX(bar, STAGE_B); \
    uint32_t d = sb + (s) * STAGE_B; \
    size_t ta = ((size_t)(m0b * 64 + (kt))) << 13; \
    size_t tb = ((size_t)(n0b * 64 + (kt))) << 13; \
    BULK_G2S(d,         (const char*)g_A0 + ta, 8192, bar); \
    BULK_G2S(d + 8192,  (const char*)g_A1 + ta, 8192, bar); \
    BULK_G2S(d + 16384, (const char*)g_B0 + tb, 8192, bar); \
    BULK_G2S(d + 24576, (const char*)g_B1 + tb, 8192, bar); \
} while (0)

#define DO_PASS(aF, bF) do { \
    _Pragma("unroll") \
    for (int mi = 0; mi < 2; mi++) \
        _Pragma("unroll") \
        for (int ni = 0; ni < 8; ni++) { \
            const uint32_t* bp = (bF)[ni >> 1]; \
            if (ni & 1) MMA_F16(acc[mi][ni], (aF)[mi], bp[2], bp[3]); \
            else        MMA_F16(acc[mi][ni], (aF)[mi], bp[0], bp[1]); \
        } \
} while (0)

    if (tid == 0) {
#pragma unroll
        for (int s2 = 0; s2 < NST; s2++) MBAR_INIT(mba + s2 * 8, 1);
        FENCE_ASYNC();
    }
    __syncthreads();
    if (tid == 0) {
        ISSUE_STAGE(0, 0);
        ISSUE_STAGE(1, 1);
        ISSUE_STAGE(2, 2);
    }

    const int a_row_l = lane & 15;
    const int a_k_l   = ((lane >> 4) & 1) * 16;
    const int b_row_l = (lane & 7) + ((lane >> 4) << 3);
    const int b_k_l   = (lane & 8) ? 16 : 0;

    int s = 0, ph = 0;
#pragma unroll 1
    for (int kt = 0; kt < 64; kt++) {
        MBAR_WAIT_ACQ(mba + s * 8, ph);
        const uint32_t stage = sb + s * STAGE_B;

#pragma unroll
        for (int p = 0; p < 2; p++) {
            uint32_t aH[2][4], bH[4][4];
#pragma unroll
            for (int mi = 0; mi < 2; mi++) {
                int row = m_off + mi * 16 + a_row_l;
                LDSM_X4(aH[mi][0], aH[mi][1], aH[mi][2], aH[mi][3],
                        stage + tile_off(row, p * 32 + a_k_l));
            }
#pragma unroll
            for (int ni2 = 0; ni2 < 4; ni2++) {
                int row = n_off + ni2 * 16 + b_row_l;
                LDSM_X4(bH[ni2][0], bH[ni2][1], bH[ni2][2], bH[ni2][3],
                        stage + 16384u + tile_off(row, p * 32 + b_k_l));
            }
            DO_PASS(aH, bH);                       // hi * hi

            uint32_t aL[2][4];
#pragma unroll
            for (int mi = 0; mi < 2; mi++) {
                int row = m_off + mi * 16 + a_row_l;
                LDSM_X4(aL[mi][0], aL[mi][1], aL[mi][2], aL[mi][3],
                        stage + 8192u + tile_off(row, p * 32 + a_k_l));
            }
            DO_PASS(aL, bH);                       // lo * hi

            uint32_t bL[4][4];
#pragma unroll
            for (int ni2 = 0; ni2 < 4; ni2++) {
                int row = n_off + ni2 * 16 + b_row_l;
                LDSM_X4(bL[ni2][0], bL[ni2][1], bL[ni2][2], bL[ni2][3],
                        stage + 24576u + tile_off(row, p * 32 + b_k_l));
            }
            DO_PASS(aH, bL);                       // hi * lo
        }

        __syncthreads();
        if (tid == 0 && kt + 3 < 64) ISSUE_STAGE(s, kt + 3);
        if (++s == NST) { s = 0; ph ^= 1; }
    }

    const int m0 = m0b * 128, n0 = n0b * 128;
    const int lr = lane >> 2;
    const int lc = (lane & 3) * 2;
#pragma unroll
    for (int mi = 0; mi < 2; mi++) {
        int r_lo = m0 + m_off + mi * 16 + lr;
#pragma unroll
        for (int ni = 0; ni < 8; ni++) {
            int c = n0 + n_off + ni * 8 + lc;
            float2 bb = *(const float2*)&bias1[c];
            float v0 = acc[mi][ni][0] + bb.x;
            float v1 = acc[mi][ni][1] + bb.y;
            float v2 = acc[mi][ni][2] + bb.x;
            float v3 = acc[mi][ni][3] + bb.y;
            float2 o0, o1;
            o0.x = 0.5f * v0 * (1.0f + erff(v0 * 0.7071067811865476f));
            o0.y = 0.5f * v1 * (1.0f + erff(v1 * 0.7071067811865476f));
            o1.x = 0.5f * v2 * (1.0f + erff(v2 * 0.7071067811865476f));
            o1.y = 0.5f * v3 * (1.0f + erff(v3 * 0.7071067811865476f));
            *(float2*)&g_h[(size_t)r_lo * H2DIM + c] = o0;
            *(float2*)&g_h[(size_t)(r_lo + 8) * H2DIM + c] = o1;
        }
    }
}

// ---------------- K4: GEMM2 + routing epilogue (4 tokens / warp) ----------------
__global__ __launch_bounds__(256)
void router_kernel(const float* __restrict__ w2,
                   const float* __restrict__ b2,
                   float* __restrict__ out_ew,
                   float* __restrict__ out_masks)
{
    __shared__ float w2s[NEXP][H2DIM];
    __shared__ float ssum[NEXP];
    int tid = threadIdx.x;
#pragma unroll
    for (int i = tid * 4; i < NEXP * H2DIM; i += 1024)
        *(float4*)&w2s[0][i] = *(const float4*)&w2[i];
    if (tid < NEXP) ssum[tid] = 0.f;
    __syncthreads();

    int warp = tid >> 5, lane = tid & 31;
    int t0 = blockIdx.x * 32 + warp * 4;

    float acc[4][8];
#pragma unroll
    for (int t = 0; t < 4; t++)
#pragma unroll
        for (int e = 0; e < 8; e++) acc[t][e] = 0.f;

#pragma unroll
    for (int j = 0; j < 8; j++) {
        int k = lane * 4 + j * 128;
        float4 wv[8];
#pragma unroll
        for (int e = 0; e < 8; e++) wv[e] = *(const float4*)&w2s[e][k];
#pragma unroll
        for (int t = 0; t < 4; t++) {
            float4 hv = *(const float4*)&g_h[(size_t)(t0 + t) * H2DIM + k];
#pragma unroll
            for (int e = 0; e < 8; e++)
                acc[t][e] = fmaf(hv.x, wv[e].x, fmaf(hv.y, wv[e].y,
                            fmaf(hv.z, wv[e].z, fmaf(hv.w, wv[e].w, acc[t][e]))));
        }
    }
#pragma unroll
    for (int off = 16; off; off >>= 1)
#pragma unroll
        for (int t = 0; t < 4; t++)
#pragma unroll
            for (int e = 0; e < 8; e++)
                acc[t][e] += __shfl_xor_sync(0xFFFFFFFFu, acc[t][e], off);

    if (lane < 4) {
        int token = t0 + lane;
        float ew[8];
#pragma unroll
        for (int e = 0; e < 8; e++) {
            float v = (acc[lane][e] + b2[e]) / 0.7f;
            ew[e] = fminf(fmaxf(v, -50.f), 50.f);
        }
        float4* po = (float4*)(out_ew + (size_t)token * 8);
        po[0] = make_float4(ew[0], ew[1], ew[2], ew[3]);
        po[1] = make_float4(ew[4], ew[5], ew[6], ew[7]);

        int i0 = 0; float v0 = ew[0];
#pragma unroll
        for (int e = 1; e < 8; e++) if (ew[e] > v0) { v0 = ew[e]; i0 = e; }
        int i1 = -1; float v1 = -3.4e38f;
#pragma unroll
        for (int e = 0; e < 8; e++) if (e != i0 && ew[e] > v1) { v1 = ew[e]; i1 = e; }

        float p1 = expf(v1 - v0);
        float sden = 1.0f + p1;
        float sm0 = 1.0f / sden;
        float sm1 = p1 / sden;
        float rs = fmaxf(sm0 + sm1, 1e-6f);
        float mk[8] = {0, 0, 0, 0, 0, 0, 0, 0};
        mk[i0] = sm0 / rs;
        mk[i1] = sm1 / rs;
        float4* pm = (float4*)(out_masks + (size_t)token * 8);
        pm[0] = make_float4(mk[0], mk[1], mk[2], mk[3]);
        pm[1] = make_float4(mk[4], mk[5], mk[6], mk[7]);
        atomicAdd(&ssum[i0], sm0);
        atomicAdd(&ssum[i1], sm1);
    }
    __syncthreads();
    if (tid < NEXP) atomicAdd(&g_sums[tid], ssum[tid]);
}

// ---------------- K5: usage + KL ----------------
__global__ void finish_kernel(float* __restrict__ out_tail)
{
    if (threadIdx.x == 0) {
        float total = 0.f, s[8];
#pragma unroll
        for (int e = 0; e < 8; e++) { s[e] = g_sums[e]; total += s[e]; }
        float den = fmaxf(total, 1e-6f);
        float kl = 0.f;
#pragma unroll
        for (int e = 0; e < 8; e++) {
            float u = s[e] / den;
            out_tail[1 + e] = u;
            kl += 0.125f * (logf(0.125f) - logf(fmaxf(u, 1e-6f)));
        }
        out_tail[0] = 0.01f * (kl * 0.125f);
    }
}

// ---------------- launch ----------------
extern "C" void kernel_launch(void* const* d_in, const int* in_sizes, int n_in,
                              void* d_out, int out_size)
{
    const float* x   = (const float*)d_in[0];
    const float* lnw = (const float*)d_in[1];
    const float* lnb = (const float*)d_in[2];
    const float* w1  = (const float*)d_in[3];
    const float* b1  = (const float*)d_in[4];
    const float* w2  = (const float*)d_in[5];
    const float* b2  = (const float*)d_in[6];
    float* out = (float*)d_out;

    cudaFuncSetAttribute(gemm1_mma_kernel, cudaFuncAttributeMaxDynamicSharedMemorySize, SMEM_GEMM);

    ln_a_convert_kernel<<<N_TOK, 256>>>(x, lnw, lnb);
    b_convert_kernel<<<H2DIM, 256>>>(w1);
    gemm1_mma_kernel<<<dim3(8, 256), 256, SMEM_GEMM>>>(b1);
    router_kernel<<<N_TOK / 32, 256>>>(w2, b2, out, out + (size_t)N_TOK * NEXP);
    finish_kernel<<<1, 32>>>(out + (size_t)2 * N_TOK * NEXP);
}